// round 2
// baseline (speedup 1.0000x reference)
#include <cuda_runtime.h>
#include <math.h>

// ---------------- problem constants ----------------
#define N_RBF   300
#define NBUCK   512
#define N_MAXN  100352            // 784*128
#define E_MAXE  400384            // 3128*128
#define RBF_STEP (30.0f/299.0f)
#define RBF_INV  (299.0f/30.0f)   // 1/gap
#define WIN      2.0f             // |d-c|>2 -> exp(-39.9) ~ 5e-18, negligible

// ---------------- device scratch (static globals; no runtime alloc) ----------------
__device__ float g_h  [(size_t)N_MAXN*128];
__device__ float g_t  [(size_t)E_MAXE*428];
__device__ float g_ee [(size_t)E_MAXE*128];
__device__ float g_tmp[(size_t)E_MAXE*128];
__device__ float g_W1T [3*300*428];
__device__ float g_We2T[3*428*128];
__device__ float g_Wn1T[3*128*128];
__device__ float g_Wn2T[3*128*128];
__device__ float g_WcT [3*128*128];
__device__ float g_Wr1T[128*128];
__device__ float g_P   [3*400*428];
__device__ int   g_perm[E_MAXE];
__device__ int   g_hist[2*NBUCK];

// ---------------- small utility kernels ----------------
__global__ void zero_hist_k() {
    int i = blockIdx.x*256 + threadIdx.x;
    if (i < 2*NBUCK) g_hist[i] = 0;
}

__global__ void zero_f_k(float* p, int n) {
    int i = blockIdx.x*256 + threadIdx.x;
    if (i < n) p[i] = 0.f;
}

__device__ __forceinline__ int bucket_of(float d) {
    int b = (int)(d * (512.0f/30.0f));
    return min(max(b, 0), NBUCK-1);
}

__global__ void hist_k(const float* __restrict__ dist, int E) {
    int e = blockIdx.x*256 + threadIdx.x;
    if (e < E) atomicAdd(&g_hist[bucket_of(dist[e])], 1);
}

__global__ void scan512_k() {
    __shared__ int s[NBUCK];
    int tid = threadIdx.x;
    int v0 = g_hist[tid];
    s[tid] = v0;
    __syncthreads();
    for (int off = 1; off < NBUCK; off <<= 1) {
        int v = 0;
        if (tid >= off) v = s[tid - off];
        __syncthreads();
        s[tid] += v;
        __syncthreads();
    }
    g_hist[NBUCK + tid] = s[tid] - v0;   // exclusive prefix
}

__global__ void scatter_perm_k(const float* __restrict__ dist, int E) {
    int e = blockIdx.x*256 + threadIdx.x;
    if (e < E) {
        int b = bucket_of(dist[e]);
        int pos = atomicAdd(&g_hist[NBUCK + b], 1);
        g_perm[pos] = e;
    }
}

__global__ void init_h_k(const int* __restrict__ Z, const float* __restrict__ node_emb,
                         float* __restrict__ h, int N) {
    int idx = blockIdx.x*256 + threadIdx.x;
    if (idx < N*128) {
        int n = idx >> 7, d = idx & 127;
        h[idx] = node_emb[Z[n]*128 + d];
    }
}

// dst[k*J + j] = src[j*ldsrc + off + k]
__global__ void transpose_off_k(const float* __restrict__ src, float* __restrict__ dst,
                                int J, int Kd, int ldsrc, int off) {
    int idx = blockIdx.x*256 + threadIdx.x;
    if (idx < J*Kd) {
        int k = idx / J, j = idx % J;
        dst[(size_t)k*J + j] = src[(size_t)j*ldsrc + off + k];
    }
}

// P[layer][type][j] = be1[layer][j] + sum_k edge_emb[type][k] * We1[layer][j][k]
__global__ void p_kernel(const float* __restrict__ edge_emb, const float* __restrict__ We1,
                         const float* __restrict__ be1, float* __restrict__ P) {
    int ty = blockIdx.x, layer = blockIdx.y, j = threadIdx.x;
    __shared__ float em[128];
    if (j < 128) em[j] = edge_emb[ty*128 + j];
    __syncthreads();
    if (j < 428) {
        const float* wrow = We1 + ((size_t)layer*428 + j)*428;
        float acc = be1[layer*428 + j];
        #pragma unroll 8
        for (int k = 0; k < 128; k++) acc = fmaf(em[k], wrow[k], acc);
        P[((size_t)layer*400 + ty)*428 + j] = acc;
    }
}

// ---------------- windowed RBF GEMM: t = relu(rbf(dist) @ W1T + P[etype]) ----------------
// grid: (ceil(E/128), 4), 256 threads. Edges in perm (dist-sorted) order.
__global__ void __launch_bounds__(256, 2)
t_kernel(const float* __restrict__ dist, const int* __restrict__ etype,
         const int* __restrict__ perm, const float* __restrict__ W1T,
         const float* __restrict__ P, float* __restrict__ T, int E) {
    __shared__ __align__(16) float As[8][128];
    __shared__ __align__(16) float Bs[8][128];
    __shared__ float sd[128];
    __shared__ int   sty[128];
    __shared__ float rmn[128], rmx[128];

    int tid = threadIdx.x, bx = blockIdx.x, by = blockIdx.y;
    if (tid < 128) {
        int r = bx*128 + tid;
        int rr = (r < E) ? r : (E - 1);
        int e = perm[rr];
        float d = dist[e];
        sd[tid] = d; sty[tid] = etype[e];
        rmn[tid] = d; rmx[tid] = d;
    }
    __syncthreads();
    for (int s = 64; s > 0; s >>= 1) {
        if (tid < s) {
            rmn[tid] = fminf(rmn[tid], rmn[tid+s]);
            rmx[tid] = fmaxf(rmx[tid], rmx[tid+s]);
        }
        __syncthreads();
    }
    float dmn = rmn[0], dmx = rmx[0];
    int klo = (int)ceilf((dmn - WIN) * RBF_INV); if (klo < 0) klo = 0;
    int khi = (int)floorf((dmx + WIN) * RBF_INV); if (khi > N_RBF-1) khi = N_RBF-1;

    int trow = tid >> 4, tcol = tid & 15;
    int a_row = tid >> 1, a_kg = (tid & 1) * 4;
    int b_k = tid >> 5,  b_c = (tid & 31) * 4;
    float dA = sd[a_row];
    int colg0 = by * 128;

    float acc[8][8];
    #pragma unroll
    for (int i = 0; i < 8; i++)
        #pragma unroll
        for (int j = 0; j < 8; j++) acc[i][j] = 0.f;

    for (int k0 = klo; k0 <= khi; k0 += 8) {
        float av[4];
        #pragma unroll
        for (int i = 0; i < 4; i++) {
            int k = k0 + a_kg + i;
            float diff = dA - (float)k * RBF_STEP;
            av[i] = (k < N_RBF) ? __expf(-diff*diff*RBF_INV) : 0.f;
        }
        float4 bv = make_float4(0.f, 0.f, 0.f, 0.f);
        {
            int k = k0 + b_k;
            int cg = colg0 + b_c;
            if (k < N_RBF) {
                const float* Bp = W1T + (size_t)k*428 + cg;
                if (cg + 3 < 428) bv = *(const float4*)Bp;
                else {
                    if (cg + 0 < 428) bv.x = Bp[0];
                    if (cg + 1 < 428) bv.y = Bp[1];
                    if (cg + 2 < 428) bv.z = Bp[2];
                }
            }
        }
        __syncthreads();
        #pragma unroll
        for (int i = 0; i < 4; i++) As[a_kg + i][a_row] = av[i];
        *(float4*)&Bs[b_k][b_c] = bv;
        __syncthreads();
        #pragma unroll
        for (int kk = 0; kk < 8; kk++) {
            float a[8], b[8];
            *(float4*)&a[0] = *(const float4*)&As[kk][trow*8];
            *(float4*)&a[4] = *(const float4*)&As[kk][trow*8 + 4];
            *(float4*)&b[0] = *(const float4*)&Bs[kk][tcol*8];
            *(float4*)&b[4] = *(const float4*)&Bs[kk][tcol*8 + 4];
            #pragma unroll
            for (int i = 0; i < 8; i++)
                #pragma unroll
                for (int j = 0; j < 8; j++)
                    acc[i][j] = fmaf(a[i], b[j], acc[i][j]);
        }
    }

    #pragma unroll
    for (int i = 0; i < 8; i++) {
        int row = bx*128 + trow*8 + i;
        if (row < E) {
            int ety = sty[trow*8 + i];
            const float* Pr = P + (size_t)ety * 428;
            size_t tb = (size_t)row * 428;
            #pragma unroll
            for (int jj = 0; jj < 8; jj += 4) {
                int col = colg0 + tcol*8 + jj;
                if (col + 3 < 428) {
                    float4 pv = *(const float4*)(Pr + col);
                    float4 o;
                    o.x = fmaxf(acc[i][jj+0] + pv.x, 0.f);
                    o.y = fmaxf(acc[i][jj+1] + pv.y, 0.f);
                    o.z = fmaxf(acc[i][jj+2] + pv.z, 0.f);
                    o.w = fmaxf(acc[i][jj+3] + pv.w, 0.f);
                    *(float4*)(T + tb + col) = o;
                } else {
                    #pragma unroll
                    for (int q = 0; q < 4; q++) {
                        int c = col + q;
                        if (c < 428) T[tb + c] = fmaxf(acc[i][jj+q] + Pr[c], 0.f);
                    }
                }
            }
        }
    }
}

// ---------------- generic 128-N GEMM: C[M,128] = epi(A[M,K] @ B[K,128] + bias) ----------------
// EPI: 0 = store, 1 = relu store, 2 = (acc+bias)*EE store, 3 = tanh + atomicAdd scatter to Hout[dst]
// GATHER: A row index = gidx[perm[row]]
template<int EPI, bool GATHER>
__global__ void __launch_bounds__(256, 2)
gemm128(const float* A, const float* __restrict__ B,
        const float* __restrict__ bias, float* C,
        int M, int K,
        const int* __restrict__ perm, const int* __restrict__ gidx,
        const float* __restrict__ EE, float* Hout) {
    __shared__ __align__(16) float As[8][128];
    __shared__ __align__(16) float Bs[8][128];
    __shared__ float sbias[128];

    int tid = threadIdx.x, bx = blockIdx.x;
    if (tid < 128) sbias[tid] = bias[tid];

    int trow = tid >> 4, tcol = tid & 15;
    int a_row = tid >> 1, a_kg = (tid & 1) * 4;
    int b_k = tid >> 5,  b_c = (tid & 31) * 4;

    int gr = bx*128 + a_row;
    bool arow_valid = (gr < M);
    const float* Arow = A;
    if (arow_valid) {
        int ar = GATHER ? gidx[perm[gr]] : gr;
        Arow = A + (size_t)ar * K;
    }

    float acc[8][8];
    #pragma unroll
    for (int i = 0; i < 8; i++)
        #pragma unroll
        for (int j = 0; j < 8; j++) acc[i][j] = 0.f;

    for (int k0 = 0; k0 < K; k0 += 8) {
        float4 av = make_float4(0.f, 0.f, 0.f, 0.f);
        if (arow_valid) {
            int k = k0 + a_kg;
            if (k + 3 < K) av = *(const float4*)(Arow + k);
            else {
                if (k + 0 < K) av.x = Arow[k + 0];
                if (k + 1 < K) av.y = Arow[k + 1];
                if (k + 2 < K) av.z = Arow[k + 2];
                if (k + 3 < K) av.w = Arow[k + 3];
            }
        }
        float4 bv = make_float4(0.f, 0.f, 0.f, 0.f);
        {
            int k = k0 + b_k;
            if (k < K) bv = *(const float4*)(B + (size_t)k*128 + b_c);
        }
        __syncthreads();
        As[a_kg + 0][a_row] = av.x;
        As[a_kg + 1][a_row] = av.y;
        As[a_kg + 2][a_row] = av.z;
        As[a_kg + 3][a_row] = av.w;
        *(float4*)&Bs[b_k][b_c] = bv;
        __syncthreads();
        #pragma unroll
        for (int kk = 0; kk < 8; kk++) {
            float a[8], b[8];
            *(float4*)&a[0] = *(const float4*)&As[kk][trow*8];
            *(float4*)&a[4] = *(const float4*)&As[kk][trow*8 + 4];
            *(float4*)&b[0] = *(const float4*)&Bs[kk][tcol*8];
            *(float4*)&b[4] = *(const float4*)&Bs[kk][tcol*8 + 4];
            #pragma unroll
            for (int i = 0; i < 8; i++)
                #pragma unroll
                for (int j = 0; j < 8; j++)
                    acc[i][j] = fmaf(a[i], b[j], acc[i][j]);
        }
    }

    #pragma unroll
    for (int i = 0; i < 8; i++) {
        int row = bx*128 + trow*8 + i;
        if (row < M) {
            if (EPI == 3) {
                int dg = gidx[perm[row]];
                float* Hr = Hout + (size_t)dg * 128 + tcol*8;
                #pragma unroll
                for (int j = 0; j < 8; j++) {
                    float v = tanhf(acc[i][j] + sbias[tcol*8 + j]);
                    atomicAdd(&Hr[j], v);
                }
            } else {
                size_t base = (size_t)row * 128 + tcol*8;
                #pragma unroll
                for (int jj = 0; jj < 8; jj += 4) {
                    float4 o;
                    float v0 = acc[i][jj+0] + sbias[tcol*8 + jj+0];
                    float v1 = acc[i][jj+1] + sbias[tcol*8 + jj+1];
                    float v2 = acc[i][jj+2] + sbias[tcol*8 + jj+2];
                    float v3 = acc[i][jj+3] + sbias[tcol*8 + jj+3];
                    if (EPI == 1) {
                        v0 = fmaxf(v0, 0.f); v1 = fmaxf(v1, 0.f);
                        v2 = fmaxf(v2, 0.f); v3 = fmaxf(v3, 0.f);
                    }
                    if (EPI == 2) {
                        float4 e4 = *(const float4*)(EE + base + jj);
                        v0 *= e4.x; v1 *= e4.y; v2 *= e4.z; v3 *= e4.w;
                    }
                    o.x = v0; o.y = v1; o.z = v2; o.w = v3;
                    *(float4*)(C + base + jj) = o;
                }
            }
        }
    }
}

// ---------------- readout: r[n] = dot(rr1[n], Wr2) + br2; out[gid[n]] += r ----------------
__global__ void readout2_k(const float* __restrict__ rr, const float* __restrict__ Wr2,
                           const float* __restrict__ br2, const int* __restrict__ gid,
                           float* __restrict__ out, int N) {
    __shared__ float w[128];
    int tid = threadIdx.x;
    if (tid < 128) w[tid] = Wr2[tid];
    __syncthreads();
    int warp = tid >> 5, lane = tid & 31;
    int n = blockIdx.x*4 + warp;
    if (n >= N) return;
    const float* hr = rr + (size_t)n * 128;
    float s = 0.f;
    #pragma unroll
    for (int i = 0; i < 4; i++) s = fmaf(hr[lane + i*32], w[lane + i*32], s);
    #pragma unroll
    for (int o = 16; o > 0; o >>= 1) s += __shfl_down_sync(0xffffffffu, s, o);
    if (lane == 0) atomicAdd(&out[gid[n]], s + br2[0]);
}

// ---------------- launch ----------------
extern "C" void kernel_launch(void* const* d_in, const int* in_sizes, int n_in,
                              void* d_out, int out_size) {
    const int*   Z        = (const int*)  d_in[0];
    const int*   etype    = (const int*)  d_in[1];
    const float* dist     = (const float*)d_in[2];
    const int*   src      = (const int*)  d_in[3];
    const int*   dst      = (const int*)  d_in[4];
    const int*   gid      = (const int*)  d_in[5];
    const float* node_emb = (const float*)d_in[6];
    const float* edge_emb = (const float*)d_in[7];
    const float* Wn1 = (const float*)d_in[8];
    const float* bn1 = (const float*)d_in[9];
    const float* Wn2 = (const float*)d_in[10];
    const float* bn2 = (const float*)d_in[11];
    const float* We1 = (const float*)d_in[12];
    const float* be1 = (const float*)d_in[13];
    const float* We2 = (const float*)d_in[14];
    const float* be2 = (const float*)d_in[15];
    const float* Wc  = (const float*)d_in[16];
    const float* bc  = (const float*)d_in[17];
    const float* Wr1 = (const float*)d_in[18];
    const float* br1 = (const float*)d_in[19];
    const float* Wr2 = (const float*)d_in[20];
    const float* br2 = (const float*)d_in[21];

    int N = in_sizes[0];
    int E = in_sizes[1];
    int G = out_size;
    float* out = (float*)d_out;

    void* p;
    float *h, *t, *ee, *tmp, *W1T, *We2T, *Wn1T, *Wn2T, *WcT, *Wr1T, *P;
    int *perm;
    cudaGetSymbolAddress(&p, g_h);    h    = (float*)p;
    cudaGetSymbolAddress(&p, g_t);    t    = (float*)p;
    cudaGetSymbolAddress(&p, g_ee);   ee   = (float*)p;
    cudaGetSymbolAddress(&p, g_tmp);  tmp  = (float*)p;
    cudaGetSymbolAddress(&p, g_W1T);  W1T  = (float*)p;
    cudaGetSymbolAddress(&p, g_We2T); We2T = (float*)p;
    cudaGetSymbolAddress(&p, g_Wn1T); Wn1T = (float*)p;
    cudaGetSymbolAddress(&p, g_Wn2T); Wn2T = (float*)p;
    cudaGetSymbolAddress(&p, g_WcT);  WcT  = (float*)p;
    cudaGetSymbolAddress(&p, g_Wr1T); Wr1T = (float*)p;
    cudaGetSymbolAddress(&p, g_P);    P    = (float*)p;
    cudaGetSymbolAddress(&p, g_perm); perm = (int*)p;

    // counting sort of edges by dist (for windowed RBF GEMM)
    zero_hist_k<<<(2*NBUCK + 255)/256, 256>>>();
    hist_k<<<(E + 255)/256, 256>>>(dist, E);
    scan512_k<<<1, NBUCK>>>();
    scatter_perm_k<<<(E + 255)/256, 256>>>(dist, E);

    // h init + weight transposes + P precompute
    init_h_k<<<(N*128 + 255)/256, 256>>>(Z, node_emb, h, N);
    for (int i = 0; i < 3; i++) {
        transpose_off_k<<<(428*300 + 255)/256, 256>>>(We1 + (size_t)i*428*428, W1T + (size_t)i*300*428, 428, 300, 428, 128);
        transpose_off_k<<<(128*428 + 255)/256, 256>>>(We2 + (size_t)i*128*428, We2T + (size_t)i*428*128, 128, 428, 428, 0);
        transpose_off_k<<<(128*128 + 255)/256, 256>>>(Wn1 + (size_t)i*128*128, Wn1T + (size_t)i*128*128, 128, 128, 128, 0);
        transpose_off_k<<<(128*128 + 255)/256, 256>>>(Wn2 + (size_t)i*128*128, Wn2T + (size_t)i*128*128, 128, 128, 128, 0);
        transpose_off_k<<<(128*128 + 255)/256, 256>>>(Wc  + (size_t)i*128*128, WcT  + (size_t)i*128*128, 128, 128, 128, 0);
    }
    transpose_off_k<<<(128*128 + 255)/256, 256>>>(Wr1, Wr1T, 128, 128, 128, 0);
    p_kernel<<<dim3(400, 3), 448>>>(edge_emb, We1, be1, P);

    int gE = (E + 127)/128;
    for (int i = 0; i < 3; i++) {
        // t = relu(e @ We1^T + be1)   (windowed RBF GEMM + P table)
        t_kernel<<<dim3(gE, 4), 256>>>(dist, etype, perm,
                                       W1T + (size_t)i*300*428,
                                       P + (size_t)i*400*428, t, E);
        // ee = t @ We2^T + be2
        gemm128<0, false><<<gE, 256>>>(t, We2T + (size_t)i*428*128, be2 + i*128,
                                       ee, E, 428, nullptr, nullptr, nullptr, nullptr);
        // tmp = relu(h[src] @ Wn1^T + bn1)
        gemm128<1, true><<<gE, 256>>>(h, Wn1T + (size_t)i*128*128, bn1 + i*128,
                                      tmp, E, 128, perm, src, nullptr, nullptr);
        // tmp = (tmp @ Wn2^T + bn2) * ee     (in-place safe: block-row exclusive)
        gemm128<2, false><<<gE, 256>>>(tmp, Wn2T + (size_t)i*128*128, bn2 + i*128,
                                       tmp, E, 128, nullptr, nullptr, ee, nullptr);
        // h[dst] += tanh(tmp @ Wc^T + bc)
        gemm128<3, false><<<gE, 256>>>(tmp, WcT + (size_t)i*128*128, bc + i*128,
                                       nullptr, E, 128, perm, dst, nullptr, h);
    }

    // readout
    gemm128<1, false><<<(N + 127)/128, 256>>>(h, Wr1T, br1, tmp, N, 128,
                                              nullptr, nullptr, nullptr, nullptr);
    zero_f_k<<<(G + 255)/256, 256>>>(out, G);
    readout2_k<<<(N + 3)/4, 128>>>(tmp, Wr2, br2, gid, out, N);
}

// round 4
// speedup vs baseline: 1.3209x; 1.3209x over previous
#include <cuda_runtime.h>
#include <cuda_bf16.h>
#include <math.h>
#include <stdint.h>

#define N_RBF 300
#define NBUCK 512
#define N_MAXN 100352
#define E_MAXE 400384
#define GE_MAX 3128
#define RBF_STEP (30.0f/299.0f)
#define RBF_INV  (299.0f/30.0f)
#define SLD 40   // smem row stride (bf16 units), conflict-free for ldmatrix

// ---------------- device scratch ----------------
__device__ float g_h  [(size_t)N_MAXN*128];
__device__ float g_t  [(size_t)E_MAXE*428];
__device__ float g_ee [(size_t)E_MAXE*128];
__device__ float g_tmp[(size_t)E_MAXE*128];
__device__ float g_P  [3*400*428];
__device__ int   g_perm[E_MAXE];
__device__ int   g_hist[2*NBUCK];
__device__ int   g_klo [GE_MAX];
__device__ __nv_bfloat16 g_rAh[(size_t)E_MAXE*64], g_rAl[(size_t)E_MAXE*64];
__device__ __nv_bfloat16 g_W1h[3*512*384],  g_W1l[3*512*384];
__device__ __nv_bfloat16 g_We2h[3*128*448], g_We2l[3*128*448];
__device__ __nv_bfloat16 g_Wn1h[3*128*128], g_Wn1l[3*128*128];
__device__ __nv_bfloat16 g_Wn2h[3*128*128], g_Wn2l[3*128*128];
__device__ __nv_bfloat16 g_Wch [3*128*128], g_Wcl [3*128*128];
__device__ __nv_bfloat16 g_Wr1h[128*128],   g_Wr1l[128*128];

// ---------------- helpers ----------------
__device__ __forceinline__ uint32_t smem_u32(const void* p) {
    uint32_t a;
    asm("{ .reg .u64 t; cvta.to.shared.u64 t, %1; cvt.u32.u64 %0, t; }" : "=r"(a) : "l"(p));
    return a;
}
__device__ __forceinline__ void ldmx4(uint32_t& r0, uint32_t& r1, uint32_t& r2, uint32_t& r3, uint32_t a) {
    asm volatile("ldmatrix.sync.aligned.m8n8.x4.shared.b16 {%0,%1,%2,%3}, [%4];"
        : "=r"(r0), "=r"(r1), "=r"(r2), "=r"(r3) : "r"(a));
}
__device__ __forceinline__ void mma16816(float* c, const uint32_t* a, const uint32_t* b) {
    asm volatile("mma.sync.aligned.m16n8k16.row.col.f32.bf16.bf16.f32 "
        "{%0,%1,%2,%3},{%4,%5,%6,%7},{%8,%9},{%0,%1,%2,%3};"
        : "+f"(c[0]), "+f"(c[1]), "+f"(c[2]), "+f"(c[3])
        : "r"(a[0]), "r"(a[1]), "r"(a[2]), "r"(a[3]), "r"(b[0]), "r"(b[1]));
}
__device__ __forceinline__ void pack2(float a, float b, uint32_t& h, uint32_t& l) {
    __nv_bfloat162 hb = __floats2bfloat162_rn(a, b);
    __nv_bfloat162 lb = __floats2bfloat162_rn(a - __low2float(hb), b - __high2float(hb));
    h = *reinterpret_cast<uint32_t*>(&hb);
    l = *reinterpret_cast<uint32_t*>(&lb);
}

// ---------------- utility kernels ----------------
__global__ void zero_hist_k() { int i = blockIdx.x*256 + threadIdx.x; if (i < 2*NBUCK) g_hist[i] = 0; }
__global__ void zero_f_k(float* p, int n) { int i = blockIdx.x*256 + threadIdx.x; if (i < n) p[i] = 0.f; }
__device__ __forceinline__ int bucket_of(float d) {
    int b = (int)(d * (512.0f/30.0f));
    return min(max(b, 0), NBUCK-1);
}
__global__ void hist_k(const float* __restrict__ dist, int E) {
    int e = blockIdx.x*256 + threadIdx.x;
    if (e < E) atomicAdd(&g_hist[bucket_of(dist[e])], 1);
}
__global__ void scan512_k() {
    __shared__ int s[NBUCK];
    int tid = threadIdx.x;
    int v0 = g_hist[tid];
    s[tid] = v0; __syncthreads();
    for (int off = 1; off < NBUCK; off <<= 1) {
        int v = 0;
        if (tid >= off) v = s[tid - off];
        __syncthreads(); s[tid] += v; __syncthreads();
    }
    g_hist[NBUCK + tid] = s[tid] - v0;
}
__global__ void scatter_perm_k(const float* __restrict__ dist, int E) {
    int e = blockIdx.x*256 + threadIdx.x;
    if (e < E) {
        int pos = atomicAdd(&g_hist[NBUCK + bucket_of(dist[e])], 1);
        g_perm[pos] = e;
    }
}
__global__ void init_h_k(const int* __restrict__ Z, const float* __restrict__ ne,
                         float* __restrict__ h, int N) {
    int idx = blockIdx.x*256 + threadIdx.x;
    if (idx < N*128) h[idx] = ne[Z[idx >> 7]*128 + (idx & 127)];
}
__global__ void split_pad_k(const float* __restrict__ src, __nv_bfloat16* __restrict__ dh,
                            __nv_bfloat16* __restrict__ dl,
                            int R, int Ks, int ld, int off, int Kpad, int tot) {
    int idx = blockIdx.x*256 + threadIdx.x;
    if (idx < tot) {
        int r = idx / Kpad, k = idx % Kpad;
        float v = (r < R && k < Ks) ? src[(size_t)r*ld + off + k] : 0.f;
        __nv_bfloat16 h = __float2bfloat16(v);
        dh[idx] = h;
        dl[idx] = __float2bfloat16(v - __bfloat162float(h));
    }
}
__global__ void p_kernel(const float* __restrict__ edge_emb, const float* __restrict__ We1,
                         const float* __restrict__ be1, float* __restrict__ P) {
    int ty = blockIdx.x, layer = blockIdx.y, j = threadIdx.x;
    __shared__ float em[128];
    if (j < 128) em[j] = edge_emb[ty*128 + j];
    __syncthreads();
    if (j < 428) {
        const float* wrow = We1 + ((size_t)layer*428 + j)*428;
        float acc = be1[layer*428 + j];
        #pragma unroll 8
        for (int k = 0; k < 128; k++) acc = fmaf(em[k], wrow[k], acc);
        P[((size_t)layer*400 + ty)*428 + j] = acc;
    }
}
__global__ void rbf_klo_k(const float* __restrict__ dist, int E) {
    __shared__ float s[128];
    int tid = threadIdx.x, gr = blockIdx.x*128 + tid;
    s[tid] = dist[g_perm[min(gr, E-1)]];
    __syncthreads();
    for (int o = 64; o > 0; o >>= 1) {
        if (tid < o) s[tid] = fminf(s[tid], s[tid + o]);
        __syncthreads();
    }
    if (tid == 0) {
        int k = (int)floorf((s[0] - 2.0f) * RBF_INV);
        if (k < 0) k = 0;
        g_klo[blockIdx.x] = k & ~7;
    }
}
__global__ void rbf_split_k(const float* __restrict__ dist, int E) {
    int tid = threadIdx.x, gr = blockIdx.x*128 + tid;
    float d = dist[g_perm[min(gr, E-1)]];
    int k0 = g_klo[blockIdx.x];
    float vals[64];
    #pragma unroll
    for (int i = 0; i < 64; i++) vals[i] = 0.f;
    int icen = (int)(d * RBF_INV) - k0;
    int ilo = max(0, icen - 22);
    int ihi = min(min(63, icen + 22), 299 - k0);
    for (int i = ilo; i <= ihi; i++) {
        float x = d - (float)(k0 + i) * RBF_STEP;
        vals[i] = __expf(-RBF_INV * x * x);
    }
    size_t base = (size_t)gr * 64;
    #pragma unroll
    for (int i = 0; i < 64; i += 8) {
        uint4 H, L;
        pack2(vals[i+0], vals[i+1], H.x, L.x);
        pack2(vals[i+2], vals[i+3], H.y, L.y);
        pack2(vals[i+4], vals[i+5], H.z, L.z);
        pack2(vals[i+6], vals[i+7], H.w, L.w);
        *(uint4*)(g_rAh + base + i) = H;
        *(uint4*)(g_rAl + base + i) = L;
    }
}

// ---------------- HMMA GEMM: C[M,128] = epi(A[M,Kv] @ W^T + bias) ----------------
// EPI: 0 store, 1 relu, 2 (acc+b)*EE, 3 tanh + atomicAdd scatter
template<int EPI, bool GATHER>
__global__ void __launch_bounds__(256)
gemm_mma(const float* __restrict__ A, int lda, int Kv, int Kloop,
         const __nv_bfloat16* __restrict__ Bh, const __nv_bfloat16* __restrict__ Bl, int Kpad,
         const float* __restrict__ bias, float* __restrict__ C, int M,
         const int* __restrict__ gidx, const float* __restrict__ EE, float* __restrict__ Hout) {
    __shared__ __align__(16) __nv_bfloat16 sAh[128*SLD], sAl[128*SLD], sBh[128*SLD], sBl[128*SLD];
    __shared__ const float* saptr[128];
    __shared__ float sbias[128];

    int tid = threadIdx.x, lane = tid & 31, warp = tid >> 5;
    if (tid < 128) {
        sbias[tid] = bias[tid];
        int gr = blockIdx.x*128 + tid;
        int cr = min(gr, M-1);
        int ar = GATHER ? gidx[g_perm[cr]] : cr;
        saptr[tid] = A + (size_t)ar * lda;
    }
    __syncthreads();

    uint32_t bAh = smem_u32(sAh), bAl = smem_u32(sAl);
    uint32_t bBh = smem_u32(sBh), bBl = smem_u32(sBl);
    int m0 = (warp >> 2) * 64, n0 = (warp & 3) * 32;
    int arow = lane & 15, acol = (lane >> 4) << 3;
    int brow = (lane & 7) + ((lane >> 1) & 8), bcol = lane & 8;
    uint32_t aoff[4];
    #pragma unroll
    for (int mi = 0; mi < 4; mi++) aoff[mi] = ((m0 + mi*16 + arow)*SLD + acol) * 2;
    uint32_t boff0 = ((n0 + brow)*SLD + bcol) * 2;
    uint32_t boff1 = ((n0 + 16 + brow)*SLD + bcol) * 2;

    float acc[4][4][4];
    #pragma unroll
    for (int mi = 0; mi < 4; mi++)
        #pragma unroll
        for (int ni = 0; ni < 4; ni++)
            #pragma unroll
            for (int q = 0; q < 4; q++) acc[mi][ni][q] = 0.f;

    for (int k0 = 0; k0 < Kloop; k0 += 32) {
        uint2 rAh[4], rAl[4];
        #pragma unroll
        for (int i = 0; i < 4; i++) {
            int row = i*32 + (tid >> 3);
            int k = k0 + ((tid & 7) << 2);
            const float* ap = saptr[row];
            float4 f;
            if (k + 3 < Kv) f = *(const float4*)(ap + k);
            else {
                f.x = (k+0 < Kv) ? ap[k+0] : 0.f;
                f.y = (k+1 < Kv) ? ap[k+1] : 0.f;
                f.z = (k+2 < Kv) ? ap[k+2] : 0.f;
                f.w = (k+3 < Kv) ? ap[k+3] : 0.f;
            }
            pack2(f.x, f.y, rAh[i].x, rAl[i].x);
            pack2(f.z, f.w, rAh[i].y, rAl[i].y);
        }
        uint4 rBh[2], rBl[2];
        #pragma unroll
        for (int i = 0; i < 2; i++) {
            int row = i*64 + (tid >> 2);
            int k = k0 + ((tid & 3) << 3);
            rBh[i] = *(const uint4*)(Bh + (size_t)row*Kpad + k);
            rBl[i] = *(const uint4*)(Bl + (size_t)row*Kpad + k);
        }
        __syncthreads();
        #pragma unroll
        for (int i = 0; i < 4; i++) {
            int o = (i*32 + (tid >> 3))*SLD + ((tid & 7) << 2);
            *(uint2*)&sAh[o] = rAh[i];
            *(uint2*)&sAl[o] = rAl[i];
        }
        #pragma unroll
        for (int i = 0; i < 2; i++) {
            int o = (i*64 + (tid >> 2))*SLD + ((tid & 3) << 3);
            *(uint4*)&sBh[o] = rBh[i];
            *(uint4*)&sBl[o] = rBl[i];
        }
        __syncthreads();
        #pragma unroll
        for (int ks = 0; ks < 2; ks++) {
            uint32_t ah[4][4], al[4][4], bh[8], bl[8];
            #pragma unroll
            for (int mi = 0; mi < 4; mi++) {
                ldmx4(ah[mi][0], ah[mi][1], ah[mi][2], ah[mi][3], bAh + aoff[mi] + ks*32);
                ldmx4(al[mi][0], al[mi][1], al[mi][2], al[mi][3], bAl + aoff[mi] + ks*32);
            }
            ldmx4(bh[0], bh[1], bh[2], bh[3], bBh + boff0 + ks*32);
            ldmx4(bh[4], bh[5], bh[6], bh[7], bBh + boff1 + ks*32);
            ldmx4(bl[0], bl[1], bl[2], bl[3], bBl + boff0 + ks*32);
            ldmx4(bl[4], bl[5], bl[6], bl[7], bBl + boff1 + ks*32);
            #pragma unroll
            for (int mi = 0; mi < 4; mi++)
                #pragma unroll
                for (int ni = 0; ni < 4; ni++) {
                    mma16816(acc[mi][ni], ah[mi], &bh[ni*2]);
                    mma16816(acc[mi][ni], ah[mi], &bl[ni*2]);
                    mma16816(acc[mi][ni], al[mi], &bh[ni*2]);
                }
        }
        __syncthreads();
    }

    // epilogue
    int rowb = blockIdx.x*128 + m0;
    #pragma unroll
    for (int mi = 0; mi < 4; mi++) {
        #pragma unroll
        for (int half = 0; half < 2; half++) {
            int row = rowb + mi*16 + (lane >> 2) + half*8;
            if (row < M) {
                if (EPI == 3) {
                    int dg = gidx[g_perm[row]];
                    float* Hr = Hout + (size_t)dg * 128;
                    #pragma unroll
                    for (int ni = 0; ni < 4; ni++) {
                        int col = n0 + ni*8 + (lane & 3)*2;
                        atomicAdd(Hr + col,     tanhf(acc[mi][ni][half*2+0] + sbias[col]));
                        atomicAdd(Hr + col + 1, tanhf(acc[mi][ni][half*2+1] + sbias[col+1]));
                    }
                } else {
                    size_t cb = (size_t)row * 128;
                    #pragma unroll
                    for (int ni = 0; ni < 4; ni++) {
                        int col = n0 + ni*8 + (lane & 3)*2;
                        float v0 = acc[mi][ni][half*2+0] + sbias[col];
                        float v1 = acc[mi][ni][half*2+1] + sbias[col+1];
                        if (EPI == 1) { v0 = fmaxf(v0, 0.f); v1 = fmaxf(v1, 0.f); }
                        if (EPI == 2) {
                            float2 e2 = *(const float2*)(EE + cb + col);
                            v0 *= e2.x; v1 *= e2.y;
                        }
                        float2 o = make_float2(v0, v1);
                        *(float2*)(C + cb + col) = o;
                    }
                }
            }
        }
    }
}

// ---------------- t GEMM: t[:, by*128..] = relu(rbfA @ W1^T + P[etype]) ----------------
__global__ void __launch_bounds__(256)
tgemm_mma(const __nv_bfloat16* __restrict__ Wh, const __nv_bfloat16* __restrict__ Wl,
          const float* __restrict__ P, const int* __restrict__ etype,
          float* __restrict__ T, int E) {
    __shared__ __align__(16) __nv_bfloat16 sAh[128*SLD], sAl[128*SLD], sBh[128*SLD], sBl[128*SLD];

    int tid = threadIdx.x, lane = tid & 31, warp = tid >> 5;
    int klo = g_klo[blockIdx.x];

    uint32_t bAh = smem_u32(sAh), bAl = smem_u32(sAl);
    uint32_t bBh = smem_u32(sBh), bBl = smem_u32(sBl);
    int m0 = (warp >> 2) * 64, n0 = (warp & 3) * 32;
    int arow = lane & 15, acol = (lane >> 4) << 3;
    int brow = (lane & 7) + ((lane >> 1) & 8), bcol = lane & 8;
    uint32_t aoff[4];
    #pragma unroll
    for (int mi = 0; mi < 4; mi++) aoff[mi] = ((m0 + mi*16 + arow)*SLD + acol) * 2;
    uint32_t boff0 = ((n0 + brow)*SLD + bcol) * 2;
    uint32_t boff1 = ((n0 + 16 + brow)*SLD + bcol) * 2;

    float acc[4][4][4];
    #pragma unroll
    for (int mi = 0; mi < 4; mi++)
        #pragma unroll
        for (int ni = 0; ni < 4; ni++)
            #pragma unroll
            for (int q = 0; q < 4; q++) acc[mi][ni][q] = 0.f;

    #pragma unroll
    for (int k0 = 0; k0 < 64; k0 += 32) {
        uint4 rAh[2], rAl[2], rBh[2], rBl[2];
        #pragma unroll
        for (int i = 0; i < 2; i++) {
            int row = i*64 + (tid >> 2);
            int cg = (tid & 3) << 3;
            size_t ao = (size_t)(blockIdx.x*128 + row)*64 + k0 + cg;
            rAh[i] = *(const uint4*)(g_rAh + ao);
            rAl[i] = *(const uint4*)(g_rAl + ao);
            size_t bo = (size_t)(blockIdx.y*128 + row)*384 + klo + k0 + cg;
            rBh[i] = *(const uint4*)(Wh + bo);
            rBl[i] = *(const uint4*)(Wl + bo);
        }
        __syncthreads();
        #pragma unroll
        for (int i = 0; i < 2; i++) {
            int o = (i*64 + (tid >> 2))*SLD + ((tid & 3) << 3);
            *(uint4*)&sAh[o] = rAh[i];
            *(uint4*)&sAl[o] = rAl[i];
            *(uint4*)&sBh[o] = rBh[i];
            *(uint4*)&sBl[o] = rBl[i];
        }
        __syncthreads();
        #pragma unroll
        for (int ks = 0; ks < 2; ks++) {
            uint32_t ah[4][4], al[4][4], bh[8], bl[8];
            #pragma unroll
            for (int mi = 0; mi < 4; mi++) {
                ldmx4(ah[mi][0], ah[mi][1], ah[mi][2], ah[mi][3], bAh + aoff[mi] + ks*32);
                ldmx4(al[mi][0], al[mi][1], al[mi][2], al[mi][3], bAl + aoff[mi] + ks*32);
            }
            ldmx4(bh[0], bh[1], bh[2], bh[3], bBh + boff0 + ks*32);
            ldmx4(bh[4], bh[5], bh[6], bh[7], bBh + boff1 + ks*32);
            ldmx4(bl[0], bl[1], bl[2], bl[3], bBl + boff0 + ks*32);
            ldmx4(bl[4], bl[5], bl[6], bl[7], bBl + boff1 + ks*32);
            #pragma unroll
            for (int mi = 0; mi < 4; mi++)
                #pragma unroll
                for (int ni = 0; ni < 4; ni++) {
                    mma16816(acc[mi][ni], ah[mi], &bh[ni*2]);
                    mma16816(acc[mi][ni], ah[mi], &bl[ni*2]);
                    mma16816(acc[mi][ni], al[mi], &bh[ni*2]);
                }
        }
        __syncthreads();
    }

    int rowb = blockIdx.x*128 + m0;
    int colb = blockIdx.y*128 + n0;
    #pragma unroll
    for (int mi = 0; mi < 4; mi++) {
        #pragma unroll
        for (int half = 0; half < 2; half++) {
            int row = rowb + mi*16 + (lane >> 2) + half*8;
            if (row < E) {
                int ety = etype[g_perm[row]];
                const float* Pr = P + (size_t)ety * 428;
                size_t tb = (size_t)row * 428;
                #pragma unroll
                for (int ni = 0; ni < 4; ni++) {
                    int col = colb + ni*8 + (lane & 3)*2;
                    if (col < 428) {
                        float v0 = fmaxf(acc[mi][ni][half*2+0] + Pr[col], 0.f);
                        float v1 = fmaxf(acc[mi][ni][half*2+1] + Pr[col+1], 0.f);
                        float2 o = make_float2(v0, v1);
                        *(float2*)(T + tb + col) = o;
                    }
                }
            }
        }
    }
}

__global__ void readout2_k(const float* __restrict__ rr, const float* __restrict__ Wr2,
                           const float* __restrict__ br2, const int* __restrict__ gid,
                           float* __restrict__ out, int N) {
    __shared__ float w[128];
    int tid = threadIdx.x;
    if (tid < 128) w[tid] = Wr2[tid];
    __syncthreads();
    int warp = tid >> 5, lane = tid & 31;
    int n = blockIdx.x*4 + warp;
    if (n >= N) return;
    const float* hr = rr + (size_t)n * 128;
    float s = 0.f;
    #pragma unroll
    for (int i = 0; i < 4; i++) s = fmaf(hr[lane + i*32], w[lane + i*32], s);
    #pragma unroll
    for (int o = 16; o > 0; o >>= 1) s += __shfl_down_sync(0xffffffffu, s, o);
    if (lane == 0) atomicAdd(&out[gid[n]], s + br2[0]);
}

// ---------------- launch ----------------
extern "C" void kernel_launch(void* const* d_in, const int* in_sizes, int n_in,
                              void* d_out, int out_size) {
    const int*   Z     = (const int*)  d_in[0];
    const int*   etype = (const int*)  d_in[1];
    const float* dist  = (const float*)d_in[2];
    const int*   src   = (const int*)  d_in[3];
    const int*   dst   = (const int*)  d_in[4];
    const int*   gid   = (const int*)  d_in[5];
    const float* node_emb = (const float*)d_in[6];
    const float* edge_emb = (const float*)d_in[7];
    const float* Wn1 = (const float*)d_in[8];
    const float* bn1 = (const float*)d_in[9];
    const float* Wn2 = (const float*)d_in[10];
    const float* bn2 = (const float*)d_in[11];
    const float* We1 = (const float*)d_in[12];
    const float* be1 = (const float*)d_in[13];
    const float* We2 = (const float*)d_in[14];
    const float* be2 = (const float*)d_in[15];
    const float* Wc  = (const float*)d_in[16];
    const float* bc  = (const float*)d_in[17];
    const float* Wr1 = (const float*)d_in[18];
    const float* br1 = (const float*)d_in[19];
    const float* Wr2 = (const float*)d_in[20];
    const float* br2 = (const float*)d_in[21];

    int N = in_sizes[0], E = in_sizes[1], G = out_size;
    float* out = (float*)d_out;

    void* p;
    float *h, *t, *ee, *tmp, *P;
    __nv_bfloat16 *W1h,*W1l,*We2h,*We2l,*Wn1h,*Wn1l,*Wn2h,*Wn2l,*Wch,*Wcl,*Wr1h,*Wr1l;
    cudaGetSymbolAddress(&p, g_h);   h   = (float*)p;
    cudaGetSymbolAddress(&p, g_t);   t   = (float*)p;
    cudaGetSymbolAddress(&p, g_ee);  ee  = (float*)p;
    cudaGetSymbolAddress(&p, g_tmp); tmp = (float*)p;
    cudaGetSymbolAddress(&p, g_P);   P   = (float*)p;
    cudaGetSymbolAddress(&p, g_W1h);  W1h  = (__nv_bfloat16*)p;
    cudaGetSymbolAddress(&p, g_W1l);  W1l  = (__nv_bfloat16*)p;
    cudaGetSymbolAddress(&p, g_We2h); We2h = (__nv_bfloat16*)p;
    cudaGetSymbolAddress(&p, g_We2l); We2l = (__nv_bfloat16*)p;
    cudaGetSymbolAddress(&p, g_Wn1h); Wn1h = (__nv_bfloat16*)p;
    cudaGetSymbolAddress(&p, g_Wn1l); Wn1l = (__nv_bfloat16*)p;
    cudaGetSymbolAddress(&p, g_Wn2h); Wn2h = (__nv_bfloat16*)p;
    cudaGetSymbolAddress(&p, g_Wn2l); Wn2l = (__nv_bfloat16*)p;
    cudaGetSymbolAddress(&p, g_Wch);  Wch  = (__nv_bfloat16*)p;
    cudaGetSymbolAddress(&p, g_Wcl);  Wcl  = (__nv_bfloat16*)p;
    cudaGetSymbolAddress(&p, g_Wr1h); Wr1h = (__nv_bfloat16*)p;
    cudaGetSymbolAddress(&p, g_Wr1l); Wr1l = (__nv_bfloat16*)p;

    // edge sort by dist
    zero_hist_k<<<(2*NBUCK + 255)/256, 256>>>();
    hist_k<<<(E + 255)/256, 256>>>(dist, E);
    scan512_k<<<1, NBUCK>>>();
    scatter_perm_k<<<(E + 255)/256, 256>>>(dist, E);

    int gE = (E + 127)/128;
    init_h_k<<<(N*128 + 255)/256, 256>>>(Z, node_emb, h, N);
    for (int i = 0; i < 3; i++) {
        split_pad_k<<<(512*384 + 255)/256, 256>>>(We1 + (size_t)i*428*428, W1h + (size_t)i*512*384, W1l + (size_t)i*512*384, 428, 300, 428, 128, 384, 512*384);
        split_pad_k<<<(128*448 + 255)/256, 256>>>(We2 + (size_t)i*128*428, We2h + (size_t)i*128*448, We2l + (size_t)i*128*448, 128, 428, 428, 0, 448, 128*448);
        split_pad_k<<<(128*128 + 255)/256, 256>>>(Wn1 + (size_t)i*128*128, Wn1h + (size_t)i*128*128, Wn1l + (size_t)i*128*128, 128, 128, 128, 0, 128, 128*128);
        split_pad_k<<<(128*128 + 255)/256, 256>>>(Wn2 + (size_t)i*128*128, Wn2h + (size_t)i*128*128, Wn2l + (size_t)i*128*128, 128, 128, 128, 0, 128, 128*128);
        split_pad_k<<<(128*128 + 255)/256, 256>>>(Wc  + (size_t)i*128*128, Wch  + (size_t)i*128*128, Wcl  + (size_t)i*128*128, 128, 128, 128, 0, 128, 128*128);
    }
    split_pad_k<<<(128*128 + 255)/256, 256>>>(Wr1, Wr1h, Wr1l, 128, 128, 128, 0, 128, 128*128);
    p_kernel<<<dim3(400, 3), 448>>>(edge_emb, We1, be1, P);
    rbf_klo_k<<<gE, 128>>>(dist, E);
    rbf_split_k<<<gE, 128>>>(dist, E);

    for (int i = 0; i < 3; i++) {
        tgemm_mma<<<dim3(gE, 4), 256>>>(W1h + (size_t)i*512*384, W1l + (size_t)i*512*384,
                                        P + (size_t)i*400*428, etype, t, E);
        gemm_mma<0,false><<<gE, 256>>>(t, 428, 428, 448,
            We2h + (size_t)i*128*448, We2l + (size_t)i*128*448, 448,
            be2 + i*128, ee, E, nullptr, nullptr, nullptr);
        gemm_mma<1,true><<<gE, 256>>>(h, 128, 128, 128,
            Wn1h + (size_t)i*128*128, Wn1l + (size_t)i*128*128, 128,
            bn1 + i*128, tmp, E, src, nullptr, nullptr);
        gemm_mma<2,false><<<gE, 256>>>(tmp, 128, 128, 128,
            Wn2h + (size_t)i*128*128, Wn2l + (size_t)i*128*128, 128,
            bn2 + i*128, tmp, E, nullptr, ee, nullptr);
        gemm_mma<3,false><<<gE, 256>>>(tmp, 128, 128, 128,
            Wch + (size_t)i*128*128, Wcl + (size_t)i*128*128, 128,
            bc + i*128, nullptr, E, dst, nullptr, h);
    }

    gemm_mma<1,false><<<(N + 127)/128, 256>>>(h, 128, 128, 128,
        Wr1h, Wr1l, 128, br1, tmp, N, nullptr, nullptr, nullptr);
    zero_f_k<<<(G + 255)/256, 256>>>(out, G);
    readout2_k<<<(N + 3)/4, 128>>>(tmp, Wr2, br2, gid, out, N);
}

// round 5
// speedup vs baseline: 2.0905x; 1.5826x over previous
#include <cuda_runtime.h>
#include <cuda_bf16.h>
#include <math.h>
#include <stdint.h>

#define N_RBF 300
#define NBUCK 512
#define N_MAXN 100352
#define E_MAXE 400384
#define GE_MAX 3128
#define RBF_STEP (30.0f/299.0f)
#define RBF_INV  (299.0f/30.0f)
#define SLD 40
#define BUFB 10240
#define DSMEM2 81920

__device__ float g_h  [(size_t)N_MAXN*128];
__device__ float g_ee [(size_t)E_MAXE*128];
__device__ float g_tmp[(size_t)N_MAXN*128];
__device__ float g_P  [3*400*428];
__device__ int   g_perm[E_MAXE];
__device__ int   g_hist[2*NBUCK];
__device__ int   g_klo [GE_MAX];
__device__ __nv_bfloat16 g_tAh[(size_t)E_MAXE*448], g_tAl[(size_t)E_MAXE*448];
__device__ __nv_bfloat16 g_rAh[(size_t)E_MAXE*64],  g_rAl[(size_t)E_MAXE*64];
__device__ __nv_bfloat16 g_W1h[3*512*384],  g_W1l[3*512*384];
__device__ __nv_bfloat16 g_We2h[3*128*448], g_We2l[3*128*448];
__device__ __nv_bfloat16 g_Wn1h[3*128*128], g_Wn1l[3*128*128];
__device__ __nv_bfloat16 g_Wn2h[3*128*128], g_Wn2l[3*128*128];
__device__ __nv_bfloat16 g_Wch [3*128*128], g_Wcl [3*128*128];
__device__ __nv_bfloat16 g_Wr1h[128*128],   g_Wr1l[128*128];

__device__ __forceinline__ uint32_t smem_u32(const void* p) {
    uint32_t a;
    asm("{ .reg .u64 t; cvta.to.shared.u64 t, %1; cvt.u32.u64 %0, t; }" : "=r"(a) : "l"(p));
    return a;
}
__device__ __forceinline__ void ldmx4(uint32_t& r0, uint32_t& r1, uint32_t& r2, uint32_t& r3, uint32_t a) {
    asm volatile("ldmatrix.sync.aligned.m8n8.x4.shared.b16 {%0,%1,%2,%3}, [%4];"
        : "=r"(r0), "=r"(r1), "=r"(r2), "=r"(r3) : "r"(a));
}
__device__ __forceinline__ void mma16816(float* c, const uint32_t* a, const uint32_t* b) {
    asm volatile("mma.sync.aligned.m16n8k16.row.col.f32.bf16.bf16.f32 "
        "{%0,%1,%2,%3},{%4,%5,%6,%7},{%8,%9},{%0,%1,%2,%3};"
        : "+f"(c[0]), "+f"(c[1]), "+f"(c[2]), "+f"(c[3])
        : "r"(a[0]), "r"(a[1]), "r"(a[2]), "r"(a[3]), "r"(b[0]), "r"(b[1]));
}
__device__ __forceinline__ void pack2(float a, float b, uint32_t& h, uint32_t& l) {
    __nv_bfloat162 hb = __floats2bfloat162_rn(a, b);
    __nv_bfloat162 lb = __floats2bfloat162_rn(a - __low2float(hb), b - __high2float(hb));
    h = *reinterpret_cast<uint32_t*>(&hb);
    l = *reinterpret_cast<uint32_t*>(&lb);
}
#define CPA16(dst, src) asm volatile("cp.async.cg.shared.global [%0], [%1], 16;" :: "r"(dst), "l"(src))
#define CPC()  asm volatile("cp.async.commit_group;" ::: "memory")
#define CPW0() asm volatile("cp.async.wait_group 0;" ::: "memory")

__global__ void zero_hist_k() { int i = blockIdx.x*256 + threadIdx.x; if (i < 2*NBUCK) g_hist[i] = 0; }
__global__ void zero_f_k(float* p, int n) { int i = blockIdx.x*256 + threadIdx.x; if (i < n) p[i] = 0.f; }
__device__ __forceinline__ int bucket_of(float d) {
    int b = (int)(d * (512.0f/30.0f));
    return min(max(b, 0), NBUCK-1);
}
__global__ void hist_k(const float* __restrict__ dist, int E) {
    int e = blockIdx.x*256 + threadIdx.x;
    if (e < E) atomicAdd(&g_hist[bucket_of(dist[e])], 1);
}
__global__ void scan512_k() {
    __shared__ int s[NBUCK];
    int tid = threadIdx.x;
    int v0 = g_hist[tid];
    s[tid] = v0; __syncthreads();
    for (int off = 1; off < NBUCK; off <<= 1) {
        int v = 0;
        if (tid >= off) v = s[tid - off];
        __syncthreads(); s[tid] += v; __syncthreads();
    }
    g_hist[NBUCK + tid] = s[tid] - v0;
}
__global__ void scatter_perm_k(const float* __restrict__ dist, int E) {
    int e = blockIdx.x*256 + threadIdx.x;
    if (e < E) {
        int pos = atomicAdd(&g_hist[NBUCK + bucket_of(dist[e])], 1);
        g_perm[pos] = e;
    }
}
__global__ void init_h_k(const int* __restrict__ Z, const float* __restrict__ ne,
                         float* __restrict__ h, int N) {
    int idx = blockIdx.x*256 + threadIdx.x;
    if (idx < N*128) h[idx] = ne[Z[idx >> 7]*128 + (idx & 127)];
}
__global__ void split_pad_k(const float* __restrict__ src, __nv_bfloat16* __restrict__ dh,
                            __nv_bfloat16* __restrict__ dl,
                            int R, int Ks, int ld, int off, int Kpad, int tot) {
    int idx = blockIdx.x*256 + threadIdx.x;
    if (idx < tot) {
        int r = idx / Kpad, k = idx % Kpad;
        float v = (r < R && k < Ks) ? src[(size_t)r*ld + off + k] : 0.f;
        __nv_bfloat16 h = __float2bfloat16(v);
        dh[idx] = h;
        dl[idx] = __float2bfloat16(v - __bfloat162float(h));
    }
}
__global__ void p_kernel(const float* __restrict__ edge_emb, const float* __restrict__ We1,
                         const float* __restrict__ be1, float* __restrict__ P) {
    int ty = blockIdx.x, layer = blockIdx.y, j = threadIdx.x;
    __shared__ float em[128];
    if (j < 128) em[j] = edge_emb[ty*128 + j];
    __syncthreads();
    if (j < 428) {
        const float* wrow = We1 + ((size_t)layer*428 + j)*428;
        float acc = be1[layer*428 + j];
        #pragma unroll 8
        for (int k = 0; k < 128; k++) acc = fmaf(em[k], wrow[k], acc);
        P[((size_t)layer*400 + ty)*428 + j] = acc;
    }
}
__global__ void rbf_klo_k(const float* __restrict__ dist, int E) {
    __shared__ float s[128];
    int tid = threadIdx.x, gr = blockIdx.x*128 + tid;
    s[tid] = dist[g_perm[min(gr, E-1)]];
    __syncthreads();
    for (int o = 64; o > 0; o >>= 1) {
        if (tid < o) s[tid] = fminf(s[tid], s[tid + o]);
        __syncthreads();
    }
    if (tid == 0) {
        int k = (int)floorf((s[0] - 2.0f) * RBF_INV);
        if (k < 0) k = 0;
        g_klo[blockIdx.x] = k & ~7;
    }
}
__global__ void rbf_split_k(const float* __restrict__ dist, int E) {
    int tid = threadIdx.x, gr = blockIdx.x*128 + tid;
    float d = dist[g_perm[min(gr, E-1)]];
    int k0 = g_klo[blockIdx.x];
    float vals[64];
    #pragma unroll
    for (int i = 0; i < 64; i++) vals[i] = 0.f;
    int icen = (int)(d * RBF_INV) - k0;
    int ilo = max(0, icen - 22);
    int ihi = min(min(63, icen + 22), 299 - k0);
    for (int i = ilo; i <= ihi; i++) {
        float x = d - (float)(k0 + i) * RBF_STEP;
        vals[i] = __expf(-RBF_INV * x * x);
    }
    size_t base = (size_t)gr * 64;
    #pragma unroll
    for (int i = 0; i < 64; i += 8) {
        uint4 H, L;
        pack2(vals[i+0], vals[i+1], H.x, L.x);
        pack2(vals[i+2], vals[i+3], H.y, L.y);
        pack2(vals[i+4], vals[i+5], H.z, L.z);
        pack2(vals[i+6], vals[i+7], H.w, L.w);
        *(uint4*)(g_rAh + base + i) = H;
        *(uint4*)(g_rAl + base + i) = L;
    }
}

// EPI: 0 store, 1 relu store, 3 tanh + atomicAdd scatter to Hout[sidx[perm[row]]]
// AMODE: 0 fp32 rows direct; 1 pre-split bf16 via cp.async; 2 product Af[gidx[perm[row]]]*A2[row]
template<int EPI, int AMODE>
__global__ void __launch_bounds__(256)
gemm_mma(const float* __restrict__ Af, const __nv_bfloat16* __restrict__ Abh,
         const __nv_bfloat16* __restrict__ Abl, const float* __restrict__ A2,
         int lda, int Kloop,
         const __nv_bfloat16* __restrict__ Bh, const __nv_bfloat16* __restrict__ Bl, int Kpad,
         const float* __restrict__ bias, float* __restrict__ C, int M,
         const int* __restrict__ gidx, const int* __restrict__ sidx, float* __restrict__ Hout) {
    extern __shared__ char ds[];
    __shared__ float sbias[128];
    int tid = threadIdx.x, lane = tid & 31, warp = tid >> 5;
    if (tid < 128) sbias[tid] = bias[tid];

    uint32_t b0 = smem_u32(ds);
    uint32_t uAh = b0, uAl = b0 + 2*BUFB, uBh = b0 + 4*BUFB, uBl = b0 + 6*BUFB;

    const float *p1[4], *p2[4];
    if (AMODE == 0) {
        #pragma unroll
        for (int i = 0; i < 4; i++) {
            int r = blockIdx.x*128 + i*32 + (tid >> 3);
            p1[i] = Af + (size_t)min(r, M-1) * lda;
        }
    } else if (AMODE == 2) {
        #pragma unroll
        for (int i = 0; i < 4; i++) {
            int r = blockIdx.x*128 + i*32 + (tid >> 3);
            int rc = min(r, M-1);
            p1[i] = Af + (size_t)gidx[g_perm[rc]] * 128;
            p2[i] = A2 + (size_t)rc * 128;
        }
    }
    int akoff = (tid & 7) << 2;
    int ckoff = (tid & 3) << 3;
    int crow  = tid >> 2;
    uint32_t cdst0 = ((uint32_t)crow * SLD + ckoff) * 2;
    uint32_t cdst1 = ((uint32_t)(crow + 64) * SLD + ckoff) * 2;
    uint32_t asts[4];
    #pragma unroll
    for (int i = 0; i < 4; i++) asts[i] = ((uint32_t)(i*32 + (tid >> 3)) * SLD + akoff) * 2;

    int m0 = (warp >> 2) * 64, n0 = (warp & 3) * 32;
    int arow = lane & 15, acol = (lane >> 4) << 3;
    int brow = (lane & 7) + ((lane >> 1) & 8), bcol = lane & 8;
    uint32_t aoff[4];
    #pragma unroll
    for (int mi = 0; mi < 4; mi++) aoff[mi] = ((m0 + mi*16 + arow)*SLD + acol) * 2;
    uint32_t boff0 = ((n0 + brow)*SLD + bcol) * 2;
    uint32_t boff1 = ((n0 + 16 + brow)*SLD + bcol) * 2;

    float acc[4][4][4];
    #pragma unroll
    for (int mi = 0; mi < 4; mi++)
        #pragma unroll
        for (int ni = 0; ni < 4; ni++)
            #pragma unroll
            for (int q = 0; q < 4; q++) acc[mi][ni][q] = 0.f;

    uint2 rAh[4], rAl[4];
    int nch = Kloop >> 5;

    // prologue: chunk 0 -> buffer 0
    {
        CPA16(uBh + cdst0, Bh + (size_t)crow * Kpad + ckoff);
        CPA16(uBh + cdst1, Bh + (size_t)(crow + 64) * Kpad + ckoff);
        CPA16(uBl + cdst0, Bl + (size_t)crow * Kpad + ckoff);
        CPA16(uBl + cdst1, Bl + (size_t)(crow + 64) * Kpad + ckoff);
        if (AMODE == 1) {
            size_t r0 = (size_t)(blockIdx.x*128 + crow) * lda + ckoff;
            size_t r1 = (size_t)(blockIdx.x*128 + crow + 64) * lda + ckoff;
            CPA16(uAh + cdst0, Abh + r0); CPA16(uAh + cdst1, Abh + r1);
            CPA16(uAl + cdst0, Abl + r0); CPA16(uAl + cdst1, Abl + r1);
        }
        CPC();
        if (AMODE != 1) {
            #pragma unroll
            for (int i = 0; i < 4; i++) {
                float4 f;
                if (AMODE == 0) f = *(const float4*)(p1[i] + akoff);
                else {
                    float4 f1 = *(const float4*)(p1[i] + akoff);
                    float4 f2 = *(const float4*)(p2[i] + akoff);
                    f.x = f1.x*f2.x; f.y = f1.y*f2.y; f.z = f1.z*f2.z; f.w = f1.w*f2.w;
                }
                pack2(f.x, f.y, rAh[i].x, rAl[i].x);
                pack2(f.z, f.w, rAh[i].y, rAl[i].y);
            }
            #pragma unroll
            for (int i = 0; i < 4; i++) {
                *(uint2*)(ds + asts[i]) = rAh[i];
                *(uint2*)(ds + 2*BUFB + asts[i]) = rAl[i];
            }
        }
        CPW0();
        __syncthreads();
    }

    int buf = 0;
    for (int c = 0; c < nch; c++) {
        int k1 = (c + 1) << 5;
        bool more = (c + 1) < nch;
        if (more) {
            uint32_t bb = (uint32_t)(buf ^ 1) * BUFB;
            CPA16(uBh + bb + cdst0, Bh + (size_t)crow * Kpad + k1 + ckoff);
            CPA16(uBh + bb + cdst1, Bh + (size_t)(crow + 64) * Kpad + k1 + ckoff);
            CPA16(uBl + bb + cdst0, Bl + (size_t)crow * Kpad + k1 + ckoff);
            CPA16(uBl + bb + cdst1, Bl + (size_t)(crow + 64) * Kpad + k1 + ckoff);
            if (AMODE == 1) {
                size_t r0 = (size_t)(blockIdx.x*128 + crow) * lda + k1 + ckoff;
                size_t r1 = (size_t)(blockIdx.x*128 + crow + 64) * lda + k1 + ckoff;
                CPA16(uAh + bb + cdst0, Abh + r0); CPA16(uAh + bb + cdst1, Abh + r1);
                CPA16(uAl + bb + cdst0, Abl + r0); CPA16(uAl + bb + cdst1, Abl + r1);
            }
            CPC();
            if (AMODE != 1) {
                #pragma unroll
                for (int i = 0; i < 4; i++) {
                    float4 f;
                    if (AMODE == 0) f = *(const float4*)(p1[i] + k1 + akoff);
                    else {
                        float4 f1 = *(const float4*)(p1[i] + k1 + akoff);
                        float4 f2 = *(const float4*)(p2[i] + k1 + akoff);
                        f.x = f1.x*f2.x; f.y = f1.y*f2.y; f.z = f1.z*f2.z; f.w = f1.w*f2.w;
                    }
                    pack2(f.x, f.y, rAh[i].x, rAl[i].x);
                    pack2(f.z, f.w, rAh[i].y, rAl[i].y);
                }
            }
        }
        {
            uint32_t bb = (uint32_t)buf * BUFB;
            #pragma unroll
            for (int ks = 0; ks < 2; ks++) {
                uint32_t bh[8], bl[8];
                ldmx4(bh[0], bh[1], bh[2], bh[3], uBh + bb + boff0 + ks*32);
                ldmx4(bh[4], bh[5], bh[6], bh[7], uBh + bb + boff1 + ks*32);
                ldmx4(bl[0], bl[1], bl[2], bl[3], uBl + bb + boff0 + ks*32);
                ldmx4(bl[4], bl[5], bl[6], bl[7], uBl + bb + boff1 + ks*32);
                #pragma unroll
                for (int mi = 0; mi < 4; mi++) {
                    uint32_t ah[4], al[4];
                    ldmx4(ah[0], ah[1], ah[2], ah[3], uAh + bb + aoff[mi] + ks*32);
                    ldmx4(al[0], al[1], al[2], al[3], uAl + bb + aoff[mi] + ks*32);
                    #pragma unroll
                    for (int ni = 0; ni < 4; ni++) {
                        mma16816(acc[mi][ni], ah, &bh[ni*2]);
                        mma16816(acc[mi][ni], ah, &bl[ni*2]);
                        mma16816(acc[mi][ni], al, &bh[ni*2]);
                    }
                }
            }
        }
        if (more) {
            if (AMODE != 1) {
                uint32_t bb = (uint32_t)(buf ^ 1) * BUFB;
                #pragma unroll
                for (int i = 0; i < 4; i++) {
                    *(uint2*)(ds + bb + asts[i]) = rAh[i];
                    *(uint2*)(ds + 2*BUFB + bb + asts[i]) = rAl[i];
                }
            }
            CPW0();
            __syncthreads();
            buf ^= 1;
        }
    }

    int rowb = blockIdx.x*128 + m0;
    #pragma unroll
    for (int mi = 0; mi < 4; mi++) {
        #pragma unroll
        for (int half = 0; half < 2; half++) {
            int row = rowb + mi*16 + (lane >> 2) + half*8;
            if (row < M) {
                if (EPI == 3) {
                    int dg = sidx[g_perm[row]];
                    float* Hr = Hout + (size_t)dg * 128;
                    #pragma unroll
                    for (int ni = 0; ni < 4; ni++) {
                        int col = n0 + ni*8 + (lane & 3)*2;
                        atomicAdd(Hr + col,     tanhf(acc[mi][ni][half*2+0] + sbias[col]));
                        atomicAdd(Hr + col + 1, tanhf(acc[mi][ni][half*2+1] + sbias[col+1]));
                    }
                } else {
                    size_t cb = (size_t)row * 128;
                    #pragma unroll
                    for (int ni = 0; ni < 4; ni++) {
                        int col = n0 + ni*8 + (lane & 3)*2;
                        float v0 = acc[mi][ni][half*2+0] + sbias[col];
                        float v1 = acc[mi][ni][half*2+1] + sbias[col+1];
                        if (EPI == 1) { v0 = fmaxf(v0, 0.f); v1 = fmaxf(v1, 0.f); }
                        float2 o = make_float2(v0, v1);
                        *(float2*)(C + cb + col) = o;
                    }
                }
            }
        }
    }
}

__global__ void __launch_bounds__(256)
tgemm_mma(const __nv_bfloat16* __restrict__ Wh, const __nv_bfloat16* __restrict__ Wl,
          const float* __restrict__ P, const int* __restrict__ etype, int E) {
    extern __shared__ char ds[];
    int tid = threadIdx.x, lane = tid & 31, warp = tid >> 5;
    int klo = g_klo[blockIdx.x];

    uint32_t b0 = smem_u32(ds);
    uint32_t uAh = b0, uAl = b0 + 2*BUFB, uBh = b0 + 4*BUFB, uBl = b0 + 6*BUFB;
    int ckoff = (tid & 3) << 3;
    int crow  = tid >> 2;
    uint32_t cdst0 = ((uint32_t)crow * SLD + ckoff) * 2;
    uint32_t cdst1 = ((uint32_t)(crow + 64) * SLD + ckoff) * 2;

    int m0 = (warp >> 2) * 64, n0 = (warp & 3) * 32;
    int arow = lane & 15, acol = (lane >> 4) << 3;
    int brow = (lane & 7) + ((lane >> 1) & 8), bcol = lane & 8;
    uint32_t aoff[4];
    #pragma unroll
    for (int mi = 0; mi < 4; mi++) aoff[mi] = ((m0 + mi*16 + arow)*SLD + acol) * 2;
    uint32_t boff0 = ((n0 + brow)*SLD + bcol) * 2;
    uint32_t boff1 = ((n0 + 16 + brow)*SLD + bcol) * 2;

    #pragma unroll
    for (int c = 0; c < 2; c++) {
        int k0 = c * 32;
        uint32_t bb = (uint32_t)c * BUFB;
        size_t a0 = (size_t)(blockIdx.x*128 + crow) * 64 + k0 + ckoff;
        size_t a1 = (size_t)(blockIdx.x*128 + crow + 64) * 64 + k0 + ckoff;
        size_t w0 = (size_t)(blockIdx.y*128 + crow) * 384 + klo + k0 + ckoff;
        size_t w1 = (size_t)(blockIdx.y*128 + crow + 64) * 384 + klo + k0 + ckoff;
        CPA16(uAh + bb + cdst0, g_rAh + a0); CPA16(uAh + bb + cdst1, g_rAh + a1);
        CPA16(uAl + bb + cdst0, g_rAl + a0); CPA16(uAl + bb + cdst1, g_rAl + a1);
        CPA16(uBh + bb + cdst0, Wh + w0);    CPA16(uBh + bb + cdst1, Wh + w1);
        CPA16(uBl + bb + cdst0, Wl + w0);    CPA16(uBl + bb + cdst1, Wl + w1);
    }
    CPC(); CPW0();
    __syncthreads();

    float acc[4][4][4];
    #pragma unroll
    for (int mi = 0; mi < 4; mi++)
        #pragma unroll
        for (int ni = 0; ni < 4; ni++)
            #pragma unroll
            for (int q = 0; q < 4; q++) acc[mi][ni][q] = 0.f;

    #pragma unroll
    for (int c = 0; c < 2; c++) {
        uint32_t bb = (uint32_t)c * BUFB;
        #pragma unroll
        for (int ks = 0; ks < 2; ks++) {
            uint32_t bh[8], bl[8];
            ldmx4(bh[0], bh[1], bh[2], bh[3], uBh + bb + boff0 + ks*32);
            ldmx4(bh[4], bh[5], bh[6], bh[7], uBh + bb + boff1 + ks*32);
            ldmx4(bl[0], bl[1], bl[2], bl[3], uBl + bb + boff0 + ks*32);
            ldmx4(bl[4], bl[5], bl[6], bl[7], uBl + bb + boff1 + ks*32);
            #pragma unroll
            for (int mi = 0; mi < 4; mi++) {
                uint32_t ah[4], al[4];
                ldmx4(ah[0], ah[1], ah[2], ah[3], uAh + bb + aoff[mi] + ks*32);
                ldmx4(al[0], al[1], al[2], al[3], uAl + bb + aoff[mi] + ks*32);
                #pragma unroll
                for (int ni = 0; ni < 4; ni++) {
                    mma16816(acc[mi][ni], ah, &bh[ni*2]);
                    mma16816(acc[mi][ni], ah, &bl[ni*2]);
                    mma16816(acc[mi][ni], al, &bh[ni*2]);
                }
            }
        }
    }

    int rowb = blockIdx.x*128 + m0;
    int colb = blockIdx.y*128 + n0;
    #pragma unroll
    for (int mi = 0; mi < 4; mi++) {
        #pragma unroll
        for (int half = 0; half < 2; half++) {
            int row = rowb + mi*16 + (lane >> 2) + half*8;
            if (row < E) {
                int ety = etype[g_perm[row]];
                const float* Pr = P + (size_t)ety * 428;
                size_t tb = (size_t)row * 448;
                #pragma unroll
                for (int ni = 0; ni < 4; ni++) {
                    int col = colb + ni*8 + (lane & 3)*2;
                    if (col < 448) {
                        float v0 = 0.f, v1 = 0.f;
                        if (col < 428) {
                            v0 = fmaxf(acc[mi][ni][half*2+0] + Pr[col], 0.f);
                            v1 = fmaxf(acc[mi][ni][half*2+1] + Pr[col+1], 0.f);
                        }
                        uint32_t H, L;
                        pack2(v0, v1, H, L);
                        *(uint32_t*)(g_tAh + tb + col) = H;
                        *(uint32_t*)(g_tAl + tb + col) = L;
                    }
                }
            }
        }
    }
}

__global__ void readout2_k(const float* __restrict__ rr, const float* __restrict__ Wr2,
                           const float* __restrict__ br2, const int* __restrict__ gid,
                           float* __restrict__ out, int N) {
    __shared__ float w[128];
    int tid = threadIdx.x;
    if (tid < 128) w[tid] = Wr2[tid];
    __syncthreads();
    int warp = tid >> 5, lane = tid & 31;
    int n = blockIdx.x*4 + warp;
    if (n >= N) return;
    const float* hr = rr + (size_t)n * 128;
    float s = 0.f;
    #pragma unroll
    for (int i = 0; i < 4; i++) s = fmaf(hr[lane + i*32], w[lane + i*32], s);
    #pragma unroll
    for (int o = 16; o > 0; o >>= 1) s += __shfl_down_sync(0xffffffffu, s, o);
    if (lane == 0) atomicAdd(&out[gid[n]], s + br2[0]);
}

extern "C" void kernel_launch(void* const* d_in, const int* in_sizes, int n_in,
                              void* d_out, int out_size) {
    const int*   Z     = (const int*)  d_in[0];
    const int*   etype = (const int*)  d_in[1];
    const float* dist  = (const float*)d_in[2];
    const int*   src   = (const int*)  d_in[3];
    const int*   dst   = (const int*)  d_in[4];
    const int*   gid   = (const int*)  d_in[5];
    const float* node_emb = (const float*)d_in[6];
    const float* edge_emb = (const float*)d_in[7];
    const float* Wn1 = (const float*)d_in[8];
    const float* bn1 = (const float*)d_in[9];
    const float* Wn2 = (const float*)d_in[10];
    const float* bn2 = (const float*)d_in[11];
    const float* We1 = (const float*)d_in[12];
    const float* be1 = (const float*)d_in[13];
    const float* We2 = (const float*)d_in[14];
    const float* be2 = (const float*)d_in[15];
    const float* Wc  = (const float*)d_in[16];
    const float* bc  = (const float*)d_in[17];
    const float* Wr1 = (const float*)d_in[18];
    const float* br1 = (const float*)d_in[19];
    const float* Wr2 = (const float*)d_in[20];
    const float* br2 = (const float*)d_in[21];

    int N = in_sizes[0], E = in_sizes[1], G = out_size;
    float* out = (float*)d_out;

    cudaFuncSetAttribute((const void*)tgemm_mma,     cudaFuncAttributeMaxDynamicSharedMemorySize, DSMEM2);
    cudaFuncSetAttribute((const void*)gemm_mma<0,1>, cudaFuncAttributeMaxDynamicSharedMemorySize, DSMEM2);
    cudaFuncSetAttribute((const void*)gemm_mma<1,0>, cudaFuncAttributeMaxDynamicSharedMemorySize, DSMEM2);
    cudaFuncSetAttribute((const void*)gemm_mma<0,0>, cudaFuncAttributeMaxDynamicSharedMemorySize, DSMEM2);
    cudaFuncSetAttribute((const void*)gemm_mma<3,2>, cudaFuncAttributeMaxDynamicSharedMemorySize, DSMEM2);

    void* p;
    float *h, *ee, *tmp, *P;
    __nv_bfloat16 *tAh, *tAl;
    __nv_bfloat16 *W1h,*W1l,*We2h,*We2l,*Wn1h,*Wn1l,*Wn2h,*Wn2l,*Wch,*Wcl,*Wr1h,*Wr1l;
    cudaGetSymbolAddress(&p, g_h);   h   = (float*)p;
    cudaGetSymbolAddress(&p, g_ee);  ee  = (float*)p;
    cudaGetSymbolAddress(&p, g_tmp); tmp = (float*)p;
    cudaGetSymbolAddress(&p, g_P);   P   = (float*)p;
    cudaGetSymbolAddress(&p, g_tAh); tAh = (__nv_bfloat16*)p;
    cudaGetSymbolAddress(&p, g_tAl); tAl = (__nv_bfloat16*)p;
    cudaGetSymbolAddress(&p, g_W1h);  W1h  = (__nv_bfloat16*)p;
    cudaGetSymbolAddress(&p, g_W1l);  W1l  = (__nv_bfloat16*)p;
    cudaGetSymbolAddress(&p, g_We2h); We2h = (__nv_bfloat16*)p;
    cudaGetSymbolAddress(&p, g_We2l); We2l = (__nv_bfloat16*)p;
    cudaGetSymbolAddress(&p, g_Wn1h); Wn1h = (__nv_bfloat16*)p;
    cudaGetSymbolAddress(&p, g_Wn1l); Wn1l = (__nv_bfloat16*)p;
    cudaGetSymbolAddress(&p, g_Wn2h); Wn2h = (__nv_bfloat16*)p;
    cudaGetSymbolAddress(&p, g_Wn2l); Wn2l = (__nv_bfloat16*)p;
    cudaGetSymbolAddress(&p, g_Wch);  Wch  = (__nv_bfloat16*)p;
    cudaGetSymbolAddress(&p, g_Wcl);  Wcl  = (__nv_bfloat16*)p;
    cudaGetSymbolAddress(&p, g_Wr1h); Wr1h = (__nv_bfloat16*)p;
    cudaGetSymbolAddress(&p, g_Wr1l); Wr1l = (__nv_bfloat16*)p;

    zero_hist_k<<<(2*NBUCK + 255)/256, 256>>>();
    hist_k<<<(E + 255)/256, 256>>>(dist, E);
    scan512_k<<<1, NBUCK>>>();
    scatter_perm_k<<<(E + 255)/256, 256>>>(dist, E);

    int gE = (E + 127)/128, gN = (N + 127)/128;
    init_h_k<<<(N*128 + 255)/256, 256>>>(Z, node_emb, h, N);
    for (int i = 0; i < 3; i++) {
        split_pad_k<<<(512*384 + 255)/256, 256>>>(We1 + (size_t)i*428*428, W1h + (size_t)i*512*384, W1l + (size_t)i*512*384, 428, 300, 428, 128, 384, 512*384);
        split_pad_k<<<(128*448 + 255)/256, 256>>>(We2 + (size_t)i*128*428, We2h + (size_t)i*128*448, We2l + (size_t)i*128*448, 128, 428, 428, 0, 448, 128*448);
        split_pad_k<<<(128*128 + 255)/256, 256>>>(Wn1 + (size_t)i*128*128, Wn1h + (size_t)i*128*128, Wn1l + (size_t)i*128*128, 128, 128, 128, 0, 128, 128*128);
        split_pad_k<<<(128*128 + 255)/256, 256>>>(Wn2 + (size_t)i*128*128, Wn2h + (size_t)i*128*128, Wn2l + (size_t)i*128*128, 128, 128, 128, 0, 128, 128*128);
        split_pad_k<<<(128*128 + 255)/256, 256>>>(Wc  + (size_t)i*128*128, Wch  + (size_t)i*128*128, Wcl  + (size_t)i*128*128, 128, 128, 128, 0, 128, 128*128);
    }
    split_pad_k<<<(128*128 + 255)/256, 256>>>(Wr1, Wr1h, Wr1l, 128, 128, 128, 0, 128, 128*128);
    p_kernel<<<dim3(400, 3), 448>>>(edge_emb, We1, be1, P);
    rbf_klo_k<<<gE, 128>>>(dist, E);
    rbf_split_k<<<gE, 128>>>(dist, E);

    for (int i = 0; i < 3; i++) {
        tgemm_mma<<<dim3(gE, 4), 256, DSMEM2>>>(W1h + (size_t)i*512*384, W1l + (size_t)i*512*384,
                                                P + (size_t)i*400*428, etype, E);
        gemm_mma<0,1><<<gE, 256, DSMEM2>>>(nullptr, tAh, tAl, nullptr, 448, 448,
            We2h + (size_t)i*128*448, We2l + (size_t)i*128*448, 448,
            be2 + i*128, ee, E, nullptr, nullptr, nullptr);
        gemm_mma<1,0><<<gN, 256, DSMEM2>>>(h, nullptr, nullptr, nullptr, 128, 128,
            Wn1h + (size_t)i*128*128, Wn1l + (size_t)i*128*128, 128,
            bn1 + i*128, tmp, N, nullptr, nullptr, nullptr);
        gemm_mma<0,0><<<gN, 256, DSMEM2>>>(tmp, nullptr, nullptr, nullptr, 128, 128,
            Wn2h + (size_t)i*128*128, Wn2l + (size_t)i*128*128, 128,
            bn2 + i*128, tmp, N, nullptr, nullptr, nullptr);
        gemm_mma<3,2><<<gE, 256, DSMEM2>>>(tmp, nullptr, nullptr, ee, 128, 128,
            Wch + (size_t)i*128*128, Wcl + (size_t)i*128*128, 128,
            bc + i*128, nullptr, E, src, dst, h);
    }

    gemm_mma<1,0><<<gN, 256, DSMEM2>>>(h, nullptr, nullptr, nullptr, 128, 128,
        Wr1h, Wr1l, 128, br1, tmp, N, nullptr, nullptr, nullptr);
    zero_f_k<<<(G + 255)/256, 256>>>(out, G);
    readout2_k<<<(N + 3)/4, 128>>>(tmp, Wr2, br2, gid, out, N);
}

// round 6
// speedup vs baseline: 2.6301x; 1.2581x over previous
#include <cuda_runtime.h>
#include <cuda_bf16.h>
#include <math.h>
#include <stdint.h>

#define N_RBF 300
#define NBUCK 512
#define N_MAXN 100352
#define E_MAXE 400384
#define GE_MAX 3128
#define RBF_STEP (30.0f/299.0f)
#define RBF_INV  (299.0f/30.0f)
#define SLD 40
#define BUFB 10240
#define DSMEM2 81920
#define DSMEM3 116736

__device__ float g_h  [(size_t)N_MAXN*128];
__device__ float g_ee [(size_t)E_MAXE*128];
__device__ float g_tmp[(size_t)N_MAXN*128];
__device__ float g_P  [3*400*428];
__device__ int   g_perm[E_MAXE];
__device__ int   g_hist[2*NBUCK];
__device__ int   g_klo [GE_MAX];
__device__ __nv_bfloat16 g_rAh[(size_t)E_MAXE*64],  g_rAl[(size_t)E_MAXE*64];
__device__ __nv_bfloat16 g_W1h[3*512*384],  g_W1l[3*512*384];
__device__ __nv_bfloat16 g_We2h[3*128*448], g_We2l[3*128*448];
__device__ __nv_bfloat16 g_Wn1h[3*128*128], g_Wn1l[3*128*128];
__device__ __nv_bfloat16 g_Wn2h[3*128*128], g_Wn2l[3*128*128];
__device__ __nv_bfloat16 g_Wch [3*128*128], g_Wcl [3*128*128];
__device__ __nv_bfloat16 g_Wr1h[128*128],   g_Wr1l[128*128];

__device__ __forceinline__ uint32_t smem_u32(const void* p) {
    uint32_t a;
    asm("{ .reg .u64 t; cvta.to.shared.u64 t, %1; cvt.u32.u64 %0, t; }" : "=r"(a) : "l"(p));
    return a;
}
__device__ __forceinline__ void ldmx4(uint32_t& r0, uint32_t& r1, uint32_t& r2, uint32_t& r3, uint32_t a) {
    asm volatile("ldmatrix.sync.aligned.m8n8.x4.shared.b16 {%0,%1,%2,%3}, [%4];"
        : "=r"(r0), "=r"(r1), "=r"(r2), "=r"(r3) : "r"(a));
}
__device__ __forceinline__ void mma16816(float* c, const uint32_t* a, const uint32_t* b) {
    asm volatile("mma.sync.aligned.m16n8k16.row.col.f32.bf16.bf16.f32 "
        "{%0,%1,%2,%3},{%4,%5,%6,%7},{%8,%9},{%0,%1,%2,%3};"
        : "+f"(c[0]), "+f"(c[1]), "+f"(c[2]), "+f"(c[3])
        : "r"(a[0]), "r"(a[1]), "r"(a[2]), "r"(a[3]), "r"(b[0]), "r"(b[1]));
}
__device__ __forceinline__ void pack2(float a, float b, uint32_t& h, uint32_t& l) {
    __nv_bfloat162 hb = __floats2bfloat162_rn(a, b);
    __nv_bfloat162 lb = __floats2bfloat162_rn(a - __low2float(hb), b - __high2float(hb));
    h = *reinterpret_cast<uint32_t*>(&hb);
    l = *reinterpret_cast<uint32_t*>(&lb);
}
#define CPA16(dst, src) asm volatile("cp.async.cg.shared.global [%0], [%1], 16;" :: "r"(dst), "l"(src))
#define CPC()  asm volatile("cp.async.commit_group;" ::: "memory")
#define CPW0() asm volatile("cp.async.wait_group 0;" ::: "memory")

__global__ void zero_hist_k() { int i = blockIdx.x*256 + threadIdx.x; if (i < 2*NBUCK) g_hist[i] = 0; }
__global__ void zero_f_k(float* p, int n) { int i = blockIdx.x*256 + threadIdx.x; if (i < n) p[i] = 0.f; }
__device__ __forceinline__ int bucket_of(float d) {
    int b = (int)(d * (512.0f/30.0f));
    return min(max(b, 0), NBUCK-1);
}
__global__ void hist_k(const float* __restrict__ dist, int E) {
    int e = blockIdx.x*256 + threadIdx.x;
    if (e < E) atomicAdd(&g_hist[bucket_of(dist[e])], 1);
}
__global__ void scan512_k() {
    __shared__ int s[NBUCK];
    int tid = threadIdx.x;
    int v0 = g_hist[tid];
    s[tid] = v0; __syncthreads();
    for (int off = 1; off < NBUCK; off <<= 1) {
        int v = 0;
        if (tid >= off) v = s[tid - off];
        __syncthreads(); s[tid] += v; __syncthreads();
    }
    g_hist[NBUCK + tid] = s[tid] - v0;
}
__global__ void scatter_perm_k(const float* __restrict__ dist, int E) {
    int e = blockIdx.x*256 + threadIdx.x;
    if (e < E) {
        int pos = atomicAdd(&g_hist[NBUCK + bucket_of(dist[e])], 1);
        g_perm[pos] = e;
    }
}
__global__ void init_h_k(const int* __restrict__ Z, const float* __restrict__ ne,
                         float* __restrict__ h, int N) {
    int idx = blockIdx.x*256 + threadIdx.x;
    if (idx < N*128) h[idx] = ne[Z[idx >> 7]*128 + (idx & 127)];
}
__global__ void split_pad_k(const float* __restrict__ src, __nv_bfloat16* __restrict__ dh,
                            __nv_bfloat16* __restrict__ dl,
                            int R, int Ks, int ld, int off, int Kpad, int tot) {
    int idx = blockIdx.x*256 + threadIdx.x;
    if (idx < tot) {
        int r = idx / Kpad, k = idx % Kpad;
        float v = (r < R && k < Ks) ? src[(size_t)r*ld + off + k] : 0.f;
        __nv_bfloat16 h = __float2bfloat16(v);
        dh[idx] = h;
        dl[idx] = __float2bfloat16(v - __bfloat162float(h));
    }
}
__global__ void p_kernel(const float* __restrict__ edge_emb, const float* __restrict__ We1,
                         const float* __restrict__ be1, float* __restrict__ P) {
    int ty = blockIdx.x, layer = blockIdx.y, j = threadIdx.x;
    __shared__ float em[128];
    if (j < 128) em[j] = edge_emb[ty*128 + j];
    __syncthreads();
    if (j < 428) {
        const float* wrow = We1 + ((size_t)layer*428 + j)*428;
        float acc = be1[layer*428 + j];
        #pragma unroll 8
        for (int k = 0; k < 128; k++) acc = fmaf(em[k], wrow[k], acc);
        P[((size_t)layer*400 + ty)*428 + j] = acc;
    }
}
__global__ void rbf_klo_k(const float* __restrict__ dist, int E) {
    __shared__ float s[128];
    int tid = threadIdx.x, gr = blockIdx.x*128 + tid;
    s[tid] = dist[g_perm[min(gr, E-1)]];
    __syncthreads();
    for (int o = 64; o > 0; o >>= 1) {
        if (tid < o) s[tid] = fminf(s[tid], s[tid + o]);
        __syncthreads();
    }
    if (tid == 0) {
        int k = (int)floorf((s[0] - 2.0f) * RBF_INV);
        if (k < 0) k = 0;
        g_klo[blockIdx.x] = k & ~7;
    }
}
__global__ void rbf_split_k(const float* __restrict__ dist, int E) {
    int tid = threadIdx.x, gr = blockIdx.x*128 + tid;
    float d = dist[g_perm[min(gr, E-1)]];
    int k0 = g_klo[blockIdx.x];
    float vals[64];
    #pragma unroll
    for (int i = 0; i < 64; i++) vals[i] = 0.f;
    int icen = (int)(d * RBF_INV) - k0;
    int ilo = max(0, icen - 22);
    int ihi = min(min(63, icen + 22), 299 - k0);
    for (int i = ilo; i <= ihi; i++) {
        float x = d - (float)(k0 + i) * RBF_STEP;
        vals[i] = __expf(-RBF_INV * x * x);
    }
    size_t base = (size_t)gr * 64;
    #pragma unroll
    for (int i = 0; i < 64; i += 8) {
        uint4 H, L;
        pack2(vals[i+0], vals[i+1], H.x, L.x);
        pack2(vals[i+2], vals[i+3], H.y, L.y);
        pack2(vals[i+4], vals[i+5], H.z, L.z);
        pack2(vals[i+6], vals[i+7], H.w, L.w);
        *(uint4*)(g_rAh + base + i) = H;
        *(uint4*)(g_rAl + base + i) = L;
    }
}

// ============ fused t -> ee kernel ============
// per CTA (128 edges): ee[128,128] = (relu(rbfA @ W1^T + P[etype])) @ We2^T + be2
// smem layout (bytes): sTh 0..10240, sTl 10240..20480, sAh 20480..38912, sAl 38912..57344,
// sW1h 57344(2x4608), sW1l 66560(2x4608), sW2h 75776(2x10240), sW2l 96256(2x10240)
__global__ void __launch_bounds__(256)
fused_t_ee(const __nv_bfloat16* __restrict__ W1h, const __nv_bfloat16* __restrict__ W1l,
           const __nv_bfloat16* __restrict__ W2h, const __nv_bfloat16* __restrict__ W2l,
           const float* __restrict__ P, const float* __restrict__ be2,
           const int* __restrict__ etype, float* __restrict__ ee, int E) {
    extern __shared__ char ds[];
    __shared__ int sety[128];
    __shared__ float sbias[128];
    int tid = threadIdx.x, lane = tid & 31, warp = tid >> 5, bx = blockIdx.x;
    int klo = g_klo[bx];
    if (tid < 128) {
        sety[tid] = etype[g_perm[min(bx*128 + tid, E-1)]];
        sbias[tid] = be2[tid];
    }
    uint32_t b0 = smem_u32(ds);
    uint32_t uTh = b0,          uTl = b0 + 10240;
    uint32_t uAh = b0 + 20480,  uAl = b0 + 38912;
    uint32_t uW1h = b0 + 57344, uW1l = b0 + 66560;
    uint32_t uW2h = b0 + 75776, uW2l = b0 + 96256;

    // load rbfA tile 128x64 hi/lo (stride 72)
    {
        int row = tid >> 2, k = (tid & 3) << 3;
        #pragma unroll
        for (int i = 0; i < 2; i++)
        #pragma unroll
        for (int j = 0; j < 2; j++) {
            int r = row + i*64, kk = k + j*32;
            uint32_t d = (uint32_t)(r*72 + kk)*2;
            size_t s = (size_t)(bx*128 + r)*64 + kk;
            CPA16(uAh + d, g_rAh + s);
            CPA16(uAl + d, g_rAl + s);
        }
    }
    // chunk 0: W1 rows 0..31 x 64k (stride 72), We2 128 x 32k (stride 40)
    {
        int r1 = tid >> 3, k1 = (tid & 7) << 3;
        uint32_t d1 = (uint32_t)(r1*72 + k1)*2;
        size_t s1 = (size_t)r1*384 + klo + k1;
        CPA16(uW1h + d1, W1h + s1);
        CPA16(uW1l + d1, W1l + s1);
        int r2 = tid >> 2, k2 = (tid & 3) << 3;
        uint32_t d2a = (uint32_t)(r2*SLD + k2)*2, d2b = (uint32_t)((r2+64)*SLD + k2)*2;
        size_t s2a = (size_t)r2*448 + k2, s2b = (size_t)(r2+64)*448 + k2;
        CPA16(uW2h + d2a, W2h + s2a); CPA16(uW2h + d2b, W2h + s2b);
        CPA16(uW2l + d2a, W2l + s2a); CPA16(uW2l + d2b, W2l + s2b);
    }
    CPC(); CPW0();
    __syncthreads();

    int arow = lane & 15, acol = (lane >> 4) << 3;
    int brow = (lane & 7) + ((lane >> 1) & 8), bcol = lane & 8;
    // MMA1 (8x1 warp layout: warp rows = warp*16, n covers 32 chunk cols)
    uint32_t a1off = (uint32_t)((warp*16 + arow)*72 + acol)*2;
    uint32_t b1off0 = (uint32_t)(brow*72 + bcol)*2;
    uint32_t b1off1 = (uint32_t)((16 + brow)*72 + bcol)*2;
    // MMA2 (2x4 warp layout)
    int m0 = (warp >> 2)*64, n0 = (warp & 3)*32;
    uint32_t a2off[4];
    #pragma unroll
    for (int mi = 0; mi < 4; mi++) a2off[mi] = (uint32_t)((m0 + mi*16 + arow)*SLD + acol)*2;
    uint32_t b2off0 = (uint32_t)((n0 + brow)*SLD + bcol)*2;
    uint32_t b2off1 = (uint32_t)((n0 + 16 + brow)*SLD + bcol)*2;
    int lrow = lane >> 2, lcol = (lane & 3)*2;

    float eacc[4][4][4];
    #pragma unroll
    for (int mi = 0; mi < 4; mi++)
        #pragma unroll
        for (int ni = 0; ni < 4; ni++)
            #pragma unroll
            for (int q = 0; q < 4; q++) eacc[mi][ni][q] = 0.f;

    int buf = 0;
    for (int c = 0; c < 14; c++) {
        if (c < 13) {
            uint32_t cb = (uint32_t)(buf ^ 1);
            int r1 = tid >> 3, k1 = (tid & 7) << 3;
            uint32_t d1 = cb*4608 + (uint32_t)(r1*72 + k1)*2;
            size_t s1 = (size_t)((c+1)*32 + r1)*384 + klo + k1;
            CPA16(uW1h + d1, W1h + s1);
            CPA16(uW1l + d1, W1l + s1);
            int r2 = tid >> 2, k2 = (tid & 3) << 3;
            uint32_t d2a = cb*10240 + (uint32_t)(r2*SLD + k2)*2;
            uint32_t d2b = cb*10240 + (uint32_t)((r2+64)*SLD + k2)*2;
            size_t s2a = (size_t)r2*448 + (c+1)*32 + k2;
            size_t s2b = (size_t)(r2+64)*448 + (c+1)*32 + k2;
            CPA16(uW2h + d2a, W2h + s2a); CPA16(uW2h + d2b, W2h + s2b);
            CPA16(uW2l + d2a, W2l + s2a); CPA16(uW2l + d2b, W2l + s2b);
            CPC();
        }
        // --- MMA1: t_chunk[128,32] ---
        float acc1[4][4];
        #pragma unroll
        for (int ni = 0; ni < 4; ni++)
            #pragma unroll
            for (int q = 0; q < 4; q++) acc1[ni][q] = 0.f;
        {
            uint32_t w1b = (uint32_t)buf * 4608;
            #pragma unroll
            for (int ks = 0; ks < 4; ks++) {
                uint32_t ah[4], al[4], bh[8], bl[8];
                ldmx4(ah[0], ah[1], ah[2], ah[3], uAh + a1off + ks*32);
                ldmx4(al[0], al[1], al[2], al[3], uAl + a1off + ks*32);
                ldmx4(bh[0], bh[1], bh[2], bh[3], uW1h + w1b + b1off0 + ks*32);
                ldmx4(bh[4], bh[5], bh[6], bh[7], uW1h + w1b + b1off1 + ks*32);
                ldmx4(bl[0], bl[1], bl[2], bl[3], uW1l + w1b + b1off0 + ks*32);
                ldmx4(bl[4], bl[5], bl[6], bl[7], uW1l + w1b + b1off1 + ks*32);
                #pragma unroll
                for (int ni = 0; ni < 4; ni++) {
                    mma16816(acc1[ni], ah, &bh[ni*2]);
                    mma16816(acc1[ni], ah, &bl[ni*2]);
                    mma16816(acc1[ni], al, &bh[ni*2]);
                }
            }
        }
        // --- epilogue1: +P, relu, pack hi/lo -> sT ---
        {
            int gcb = c*32;
            #pragma unroll
            for (int half = 0; half < 2; half++) {
                int r = warp*16 + lrow + half*8;
                const float* Pr = P + (size_t)sety[r]*428;
                #pragma unroll
                for (int ni = 0; ni < 4; ni++) {
                    int col = ni*8 + lcol;
                    int gcol = gcb + col;
                    float v0 = 0.f, v1 = 0.f;
                    if (gcol < 428) {
                        float2 pv = *(const float2*)(Pr + gcol);
                        v0 = fmaxf(acc1[ni][half*2+0] + pv.x, 0.f);
                        v1 = fmaxf(acc1[ni][half*2+1] + pv.y, 0.f);
                    }
                    uint32_t H, L;
                    pack2(v0, v1, H, L);
                    uint32_t doff = (uint32_t)(r*SLD + col)*2;
                    *(uint32_t*)(ds + doff) = H;
                    *(uint32_t*)(ds + 10240 + doff) = L;
                }
            }
        }
        __syncthreads();
        // --- MMA2: ee += t_chunk @ We2_chunk^T ---
        {
            uint32_t w2b = (uint32_t)buf * 10240;
            #pragma unroll
            for (int ks = 0; ks < 2; ks++) {
                uint32_t bh[8], bl[8];
                ldmx4(bh[0], bh[1], bh[2], bh[3], uW2h + w2b + b2off0 + ks*32);
                ldmx4(bh[4], bh[5], bh[6], bh[7], uW2h + w2b + b2off1 + ks*32);
                ldmx4(bl[0], bl[1], bl[2], bl[3], uW2l + w2b + b2off0 + ks*32);
                ldmx4(bl[4], bl[5], bl[6], bl[7], uW2l + w2b + b2off1 + ks*32);
                #pragma unroll
                for (int mi = 0; mi < 4; mi++) {
                    uint32_t ah[4], al[4];
                    ldmx4(ah[0], ah[1], ah[2], ah[3], uTh + a2off[mi] + ks*32);
                    ldmx4(al[0], al[1], al[2], al[3], uTl + a2off[mi] + ks*32);
                    #pragma unroll
                    for (int ni = 0; ni < 4; ni++) {
                        mma16816(eacc[mi][ni], ah, &bh[ni*2]);
                        mma16816(eacc[mi][ni], ah, &bl[ni*2]);
                        mma16816(eacc[mi][ni], al, &bh[ni*2]);
                    }
                }
            }
        }
        if (c < 13) CPW0();
        __syncthreads();
        buf ^= 1;
    }

    // epilogue: ee = eacc + be2
    int rowb = bx*128 + m0;
    #pragma unroll
    for (int mi = 0; mi < 4; mi++) {
        #pragma unroll
        for (int half = 0; half < 2; half++) {
            int row = rowb + mi*16 + lrow + half*8;
            if (row < E) {
                size_t cb = (size_t)row * 128;
                #pragma unroll
                for (int ni = 0; ni < 4; ni++) {
                    int col = n0 + ni*8 + lcol;
                    float2 o;
                    o.x = eacc[mi][ni][half*2+0] + sbias[col];
                    o.y = eacc[mi][ni][half*2+1] + sbias[col+1];
                    *(float2*)(ee + cb + col) = o;
                }
            }
        }
    }
}

// ============ generic pipelined GEMM (node MLP / mix / readout) ============
// EPI: 0 store, 1 relu store, 3 tanh + atomicAdd scatter to Hout[sidx[perm[row]]]
// AMODE: 0 fp32 rows direct; 2 product Af[gidx[perm[row]]]*A2[row]
template<int EPI, int AMODE>
__global__ void __launch_bounds__(256)
gemm_mma(const float* __restrict__ Af, const float* __restrict__ A2,
         int lda, int Kloop,
         const __nv_bfloat16* __restrict__ Bh, const __nv_bfloat16* __restrict__ Bl, int Kpad,
         const float* __restrict__ bias, float* __restrict__ C, int M,
         const int* __restrict__ gidx, const int* __restrict__ sidx, float* __restrict__ Hout) {
    extern __shared__ char ds[];
    __shared__ float sbias[128];
    int tid = threadIdx.x, lane = tid & 31, warp = tid >> 5;
    if (tid < 128) sbias[tid] = bias[tid];

    uint32_t b0 = smem_u32(ds);
    uint32_t uAh = b0, uAl = b0 + 2*BUFB, uBh = b0 + 4*BUFB, uBl = b0 + 6*BUFB;

    const float *p1[4], *p2[4];
    if (AMODE == 0) {
        #pragma unroll
        for (int i = 0; i < 4; i++) {
            int r = blockIdx.x*128 + i*32 + (tid >> 3);
            p1[i] = Af + (size_t)min(r, M-1) * lda;
        }
    } else {
        #pragma unroll
        for (int i = 0; i < 4; i++) {
            int r = blockIdx.x*128 + i*32 + (tid >> 3);
            int rc = min(r, M-1);
            p1[i] = Af + (size_t)gidx[g_perm[rc]] * 128;
            p2[i] = A2 + (size_t)rc * 128;
        }
    }
    int akoff = (tid & 7) << 2;
    int ckoff = (tid & 3) << 3;
    int crow  = tid >> 2;
    uint32_t cdst0 = ((uint32_t)crow * SLD + ckoff) * 2;
    uint32_t cdst1 = ((uint32_t)(crow + 64) * SLD + ckoff) * 2;
    uint32_t asts[4];
    #pragma unroll
    for (int i = 0; i < 4; i++) asts[i] = ((uint32_t)(i*32 + (tid >> 3)) * SLD + akoff) * 2;

    int m0 = (warp >> 2) * 64, n0 = (warp & 3) * 32;
    int arow = lane & 15, acol = (lane >> 4) << 3;
    int brow = (lane & 7) + ((lane >> 1) & 8), bcol = lane & 8;
    uint32_t aoff[4];
    #pragma unroll
    for (int mi = 0; mi < 4; mi++) aoff[mi] = ((m0 + mi*16 + arow)*SLD + acol) * 2;
    uint32_t boff0 = ((n0 + brow)*SLD + bcol) * 2;
    uint32_t boff1 = ((n0 + 16 + brow)*SLD + bcol) * 2;

    float acc[4][4][4];
    #pragma unroll
    for (int mi = 0; mi < 4; mi++)
        #pragma unroll
        for (int ni = 0; ni < 4; ni++)
            #pragma unroll
            for (int q = 0; q < 4; q++) acc[mi][ni][q] = 0.f;

    uint2 rAh[4], rAl[4];
    int nch = Kloop >> 5;

    {
        CPA16(uBh + cdst0, Bh + (size_t)crow * Kpad + ckoff);
        CPA16(uBh + cdst1, Bh + (size_t)(crow + 64) * Kpad + ckoff);
        CPA16(uBl + cdst0, Bl + (size_t)crow * Kpad + ckoff);
        CPA16(uBl + cdst1, Bl + (size_t)(crow + 64) * Kpad + ckoff);
        CPC();
        #pragma unroll
        for (int i = 0; i < 4; i++) {
            float4 f;
            if (AMODE == 0) f = *(const float4*)(p1[i] + akoff);
            else {
                float4 f1 = *(const float4*)(p1[i] + akoff);
                float4 f2 = *(const float4*)(p2[i] + akoff);
                f.x = f1.x*f2.x; f.y = f1.y*f2.y; f.z = f1.z*f2.z; f.w = f1.w*f2.w;
            }
            pack2(f.x, f.y, rAh[i].x, rAl[i].x);
            pack2(f.z, f.w, rAh[i].y, rAl[i].y);
        }
        #pragma unroll
        for (int i = 0; i < 4; i++) {
            *(uint2*)(ds + asts[i]) = rAh[i];
            *(uint2*)(ds + 2*BUFB + asts[i]) = rAl[i];
        }
        CPW0();
        __syncthreads();
    }

    int buf = 0;
    for (int c = 0; c < nch; c++) {
        int k1 = (c + 1) << 5;
        bool more = (c + 1) < nch;
        if (more) {
            uint32_t bb = (uint32_t)(buf ^ 1) * BUFB;
            CPA16(uBh + bb + cdst0, Bh + (size_t)crow * Kpad + k1 + ckoff);
            CPA16(uBh + bb + cdst1, Bh + (size_t)(crow + 64) * Kpad + k1 + ckoff);
            CPA16(uBl + bb + cdst0, Bl + (size_t)crow * Kpad + k1 + ckoff);
            CPA16(uBl + bb + cdst1, Bl + (size_t)(crow + 64) * Kpad + k1 + ckoff);
            CPC();
            #pragma unroll
            for (int i = 0; i < 4; i++) {
                float4 f;
                if (AMODE == 0) f = *(const float4*)(p1[i] + k1 + akoff);
                else {
                    float4 f1 = *(const float4*)(p1[i] + k1 + akoff);
                    float4 f2 = *(const float4*)(p2[i] + k1 + akoff);
                    f.x = f1.x*f2.x; f.y = f1.y*f2.y; f.z = f1.z*f2.z; f.w = f1.w*f2.w;
                }
                pack2(f.x, f.y, rAh[i].x, rAl[i].x);
                pack2(f.z, f.w, rAh[i].y, rAl[i].y);
            }
        }
        {
            uint32_t bb = (uint32_t)buf * BUFB;
            #pragma unroll
            for (int ks = 0; ks < 2; ks++) {
                uint32_t bh[8], bl[8];
                ldmx4(bh[0], bh[1], bh[2], bh[3], uBh + bb + boff0 + ks*32);
                ldmx4(bh[4], bh[5], bh[6], bh[7], uBh + bb + boff1 + ks*32);
                ldmx4(bl[0], bl[1], bl[2], bl[3], uBl + bb + boff0 + ks*32);
                ldmx4(bl[4], bl[5], bl[6], bl[7], uBl + bb + boff1 + ks*32);
                #pragma unroll
                for (int mi = 0; mi < 4; mi++) {
                    uint32_t ah[4], al[4];
                    ldmx4(ah[0], ah[1], ah[2], ah[3], uAh + bb + aoff[mi] + ks*32);
                    ldmx4(al[0], al[1], al[2], al[3], uAl + bb + aoff[mi] + ks*32);
                    #pragma unroll
                    for (int ni = 0; ni < 4; ni++) {
                        mma16816(acc[mi][ni], ah, &bh[ni*2]);
                        mma16816(acc[mi][ni], ah, &bl[ni*2]);
                        mma16816(acc[mi][ni], al, &bh[ni*2]);
                    }
                }
            }
        }
        if (more) {
            uint32_t bb = (uint32_t)(buf ^ 1) * BUFB;
            #pragma unroll
            for (int i = 0; i < 4; i++) {
                *(uint2*)(ds + bb + asts[i]) = rAh[i];
                *(uint2*)(ds + 2*BUFB + bb + asts[i]) = rAl[i];
            }
            CPW0();
            __syncthreads();
            buf ^= 1;
        }
    }

    int rowb = blockIdx.x*128 + m0;
    #pragma unroll
    for (int mi = 0; mi < 4; mi++) {
        #pragma unroll
        for (int half = 0; half < 2; half++) {
            int row = rowb + mi*16 + (lane >> 2) + half*8;
            if (row < M) {
                if (EPI == 3) {
                    int dg = sidx[g_perm[row]];
                    float* Hr = Hout + (size_t)dg * 128;
                    #pragma unroll
                    for (int ni = 0; ni < 4; ni++) {
                        int col = n0 + ni*8 + (lane & 3)*2;
                        atomicAdd(Hr + col,     tanhf(acc[mi][ni][half*2+0] + sbias[col]));
                        atomicAdd(Hr + col + 1, tanhf(acc[mi][ni][half*2+1] + sbias[col+1]));
                    }
                } else {
                    size_t cb = (size_t)row * 128;
                    #pragma unroll
                    for (int ni = 0; ni < 4; ni++) {
                        int col = n0 + ni*8 + (lane & 3)*2;
                        float v0 = acc[mi][ni][half*2+0] + sbias[col];
                        float v1 = acc[mi][ni][half*2+1] + sbias[col+1];
                        if (EPI == 1) { v0 = fmaxf(v0, 0.f); v1 = fmaxf(v1, 0.f); }
                        float2 o = make_float2(v0, v1);
                        *(float2*)(C + cb + col) = o;
                    }
                }
            }
        }
    }
}

__global__ void readout2_k(const float* __restrict__ rr, const float* __restrict__ Wr2,
                           const float* __restrict__ br2, const int* __restrict__ gid,
                           float* __restrict__ out, int N) {
    __shared__ float w[128];
    int tid = threadIdx.x;
    if (tid < 128) w[tid] = Wr2[tid];
    __syncthreads();
    int warp = tid >> 5, lane = tid & 31;
    int n = blockIdx.x*4 + warp;
    if (n >= N) return;
    const float* hr = rr + (size_t)n * 128;
    float s = 0.f;
    #pragma unroll
    for (int i = 0; i < 4; i++) s = fmaf(hr[lane + i*32], w[lane + i*32], s);
    #pragma unroll
    for (int o = 16; o > 0; o >>= 1) s += __shfl_down_sync(0xffffffffu, s, o);
    if (lane == 0) atomicAdd(&out[gid[n]], s + br2[0]);
}

extern "C" void kernel_launch(void* const* d_in, const int* in_sizes, int n_in,
                              void* d_out, int out_size) {
    const int*   Z     = (const int*)  d_in[0];
    const int*   etype = (const int*)  d_in[1];
    const float* dist  = (const float*)d_in[2];
    const int*   src   = (const int*)  d_in[3];
    const int*   dst   = (const int*)  d_in[4];
    const int*   gid   = (const int*)  d_in[5];
    const float* node_emb = (const float*)d_in[6];
    const float* edge_emb = (const float*)d_in[7];
    const float* Wn1 = (const float*)d_in[8];
    const float* bn1 = (const float*)d_in[9];
    const float* Wn2 = (const float*)d_in[10];
    const float* bn2 = (const float*)d_in[11];
    const float* We1 = (const float*)d_in[12];
    const float* be1 = (const float*)d_in[13];
    const float* We2 = (const float*)d_in[14];
    const float* be2 = (const float*)d_in[15];
    const float* Wc  = (const float*)d_in[16];
    const float* bc  = (const float*)d_in[17];
    const float* Wr1 = (const float*)d_in[18];
    const float* br1 = (const float*)d_in[19];
    const float* Wr2 = (const float*)d_in[20];
    const float* br2 = (const float*)d_in[21];

    int N = in_sizes[0], E = in_sizes[1], G = out_size;
    float* out = (float*)d_out;

    cudaFuncSetAttribute((const void*)fused_t_ee,    cudaFuncAttributeMaxDynamicSharedMemorySize, DSMEM3);
    cudaFuncSetAttribute((const void*)gemm_mma<1,0>, cudaFuncAttributeMaxDynamicSharedMemorySize, DSMEM2);
    cudaFuncSetAttribute((const void*)gemm_mma<0,0>, cudaFuncAttributeMaxDynamicSharedMemorySize, DSMEM2);
    cudaFuncSetAttribute((const void*)gemm_mma<3,2>, cudaFuncAttributeMaxDynamicSharedMemorySize, DSMEM2);

    void* p;
    float *h, *ee, *tmp, *P;
    __nv_bfloat16 *W1h,*W1l,*We2h,*We2l,*Wn1h,*Wn1l,*Wn2h,*Wn2l,*Wch,*Wcl,*Wr1h,*Wr1l;
    cudaGetSymbolAddress(&p, g_h);   h   = (float*)p;
    cudaGetSymbolAddress(&p, g_ee);  ee  = (float*)p;
    cudaGetSymbolAddress(&p, g_tmp); tmp = (float*)p;
    cudaGetSymbolAddress(&p, g_P);   P   = (float*)p;
    cudaGetSymbolAddress(&p, g_W1h);  W1h  = (__nv_bfloat16*)p;
    cudaGetSymbolAddress(&p, g_W1l);  W1l  = (__nv_bfloat16*)p;
    cudaGetSymbolAddress(&p, g_We2h); We2h = (__nv_bfloat16*)p;
    cudaGetSymbolAddress(&p, g_We2l); We2l = (__nv_bfloat16*)p;
    cudaGetSymbolAddress(&p, g_Wn1h); Wn1h = (__nv_bfloat16*)p;
    cudaGetSymbolAddress(&p, g_Wn1l); Wn1l = (__nv_bfloat16*)p;
    cudaGetSymbolAddress(&p, g_Wn2h); Wn2h = (__nv_bfloat16*)p;
    cudaGetSymbolAddress(&p, g_Wn2l); Wn2l = (__nv_bfloat16*)p;
    cudaGetSymbolAddress(&p, g_Wch);  Wch  = (__nv_bfloat16*)p;
    cudaGetSymbolAddress(&p, g_Wcl);  Wcl  = (__nv_bfloat16*)p;
    cudaGetSymbolAddress(&p, g_Wr1h); Wr1h = (__nv_bfloat16*)p;
    cudaGetSymbolAddress(&p, g_Wr1l); Wr1l = (__nv_bfloat16*)p;

    zero_hist_k<<<(2*NBUCK + 255)/256, 256>>>();
    hist_k<<<(E + 255)/256, 256>>>(dist, E);
    scan512_k<<<1, NBUCK>>>();
    scatter_perm_k<<<(E + 255)/256, 256>>>(dist, E);

    int gE = (E + 127)/128, gN = (N + 127)/128;
    init_h_k<<<(N*128 + 255)/256, 256>>>(Z, node_emb, h, N);
    for (int i = 0; i < 3; i++) {
        split_pad_k<<<(512*384 + 255)/256, 256>>>(We1 + (size_t)i*428*428, W1h + (size_t)i*512*384, W1l + (size_t)i*512*384, 428, 300, 428, 128, 384, 512*384);
        split_pad_k<<<(128*448 + 255)/256, 256>>>(We2 + (size_t)i*128*428, We2h + (size_t)i*128*448, We2l + (size_t)i*128*448, 128, 428, 428, 0, 448, 128*448);
        split_pad_k<<<(128*128 + 255)/256, 256>>>(Wn1 + (size_t)i*128*128, Wn1h + (size_t)i*128*128, Wn1l + (size_t)i*128*128, 128, 128, 128, 0, 128, 128*128);
        split_pad_k<<<(128*128 + 255)/256, 256>>>(Wn2 + (size_t)i*128*128, Wn2h + (size_t)i*128*128, Wn2l + (size_t)i*128*128, 128, 128, 128, 0, 128, 128*128);
        split_pad_k<<<(128*128 + 255)/256, 256>>>(Wc  + (size_t)i*128*128, Wch  + (size_t)i*128*128, Wcl  + (size_t)i*128*128, 128, 128, 128, 0, 128, 128*128);
    }
    split_pad_k<<<(128*128 + 255)/256, 256>>>(Wr1, Wr1h, Wr1l, 128, 128, 128, 0, 128, 128*128);
    p_kernel<<<dim3(400, 3), 448>>>(edge_emb, We1, be1, P);
    rbf_klo_k<<<gE, 128>>>(dist, E);
    rbf_split_k<<<gE, 128>>>(dist, E);

    for (int i = 0; i < 3; i++) {
        fused_t_ee<<<gE, 256, DSMEM3>>>(W1h + (size_t)i*512*384, W1l + (size_t)i*512*384,
                                        We2h + (size_t)i*128*448, We2l + (size_t)i*128*448,
                                        P + (size_t)i*400*428, be2 + i*128, etype, ee, E);
        gemm_mma<1,0><<<gN, 256, DSMEM2>>>(h, nullptr, 128, 128,
            Wn1h + (size_t)i*128*128, Wn1l + (size_t)i*128*128, 128,
            bn1 + i*128, tmp, N, nullptr, nullptr, nullptr);
        gemm_mma<0,0><<<gN, 256, DSMEM2>>>(tmp, nullptr, 128, 128,
            Wn2h + (size_t)i*128*128, Wn2l + (size_t)i*128*128, 128,
            bn2 + i*128, tmp, N, nullptr, nullptr, nullptr);
        gemm_mma<3,2><<<gE, 256, DSMEM2>>>(tmp, ee, 128, 128,
            Wch + (size_t)i*128*128, Wcl + (size_t)i*128*128, 128,
            bc + i*128, nullptr, E, src, dst, h);
    }

    gemm_mma<1,0><<<gN, 256, DSMEM2>>>(h, nullptr, 128, 128,
        Wr1h, Wr1l, 128, br1, tmp, N, nullptr, nullptr, nullptr);
    zero_f_k<<<(G + 255)/256, 256>>>(out, G);
    readout2_k<<<(N + 3)/4, 128>>>(tmp, Wr2, br2, gid, out, N);
}